// round 1
// baseline (speedup 1.0000x reference)
#include <cuda_runtime.h>
#include <math.h>

#define NN   4096
#define KK   16
#define DIMM 256
#define RR   8192
#define GD   8

// ---- device scratch (static, no allocation) ----
__device__ int   g_hist[17];
__device__ int   g_off[17];
__device__ int   g_cnt[16];
__device__ int   g_sorted_orig[NN];
__device__ int   g_sorted_len[NN];
__device__ float g_Wx[NN * 1024];
__device__ float g_H[2][GD][NN * DIMM];   // double-buffered h state
__device__ float g_C[GD][NN * DIMM];      // c state (element-owned, no race)
__device__ float g_Yseq[2][NN * KK * DIMM]; // gate-0 (f) fwd/bwd sequence outputs

__device__ __forceinline__ float sigm(float x) { return 1.f / (1.f + expf(-x)); }

// ---------------- sorting by length (desc) ----------------
__global__ void zero_hist_kernel() {
    if (threadIdx.x < 17) g_hist[threadIdx.x] = 0;
}

__global__ void len_hist_kernel(const int* __restrict__ indice) {
    int n = blockIdx.x * blockDim.x + threadIdx.x;
    if (n >= NN) return;
    int len = 0;
#pragma unroll
    for (int k = 0; k < KK; k++) len += (indice[n * KK + k] != -1);
    atomicAdd(&g_hist[len], 1);
}

__global__ void prefix_kernel() {
    if (threadIdx.x != 0 || blockIdx.x != 0) return;
    int run = 0;
    for (int l = 16; l >= 1; l--) { g_off[l] = run; run += g_hist[l]; }
    for (int t = 0; t < 16; t++) g_cnt[t] = g_off[t + 1] + g_hist[t + 1]; // #nodes with len > t
}

__global__ void scatter_kernel(const int* __restrict__ indice) {
    int n = blockIdx.x * blockDim.x + threadIdx.x;
    if (n >= NN) return;
    int len = 0;
#pragma unroll
    for (int k = 0; k < KK; k++) len += (indice[n * KK + k] != -1);
    int pos = atomicAdd(&g_off[len], 1);
    g_sorted_orig[pos] = n;
    g_sorted_len[pos]  = len;
}

// ---------------- W_x = x @ W_w + W_b  ([4096,256]@[256,1024]) ----------------
__global__ __launch_bounds__(256) void wx_gemm_kernel(
    const float* __restrict__ A, const float* __restrict__ B, const float* __restrict__ bias) {
    int m0 = blockIdx.x * 64, n0 = blockIdx.y * 64;
    int tid = threadIdx.x, tx = tid & 15, ty = tid >> 4;
    __shared__ __align__(16) float As[32][68];
    __shared__ __align__(16) float Bs[32][64];
    float acc[4][4];
#pragma unroll
    for (int u = 0; u < 4; u++) {
        float b = bias[n0 + tx * 4 + u];
#pragma unroll
        for (int i = 0; i < 4; i++) acc[i][u] = b;
    }
    for (int kb = 0; kb < 8; kb++) {
        int k0 = kb * 32;
        {   // A tile 64x32
            int row = tid >> 2; int kp = (tid & 3) * 8;
            float4 v0 = *(const float4*)(A + (m0 + row) * 256 + k0 + kp);
            float4 v1 = *(const float4*)(A + (m0 + row) * 256 + k0 + kp + 4);
            As[kp + 0][row] = v0.x; As[kp + 1][row] = v0.y; As[kp + 2][row] = v0.z; As[kp + 3][row] = v0.w;
            As[kp + 4][row] = v1.x; As[kp + 5][row] = v1.y; As[kp + 6][row] = v1.z; As[kp + 7][row] = v1.w;
        }
#pragma unroll
        for (int jj = 0; jj < 8; jj++) { // B tile 32x64
            int l = tid + 256 * jj; int k = l >> 6; int c = l & 63;
            Bs[k][c] = B[(k0 + k) * 1024 + n0 + c];
        }
        __syncthreads();
#pragma unroll
        for (int kk = 0; kk < 32; kk++) {
            float4 av = *(const float4*)&As[kk][ty * 4];
            float4 bv = *(const float4*)&Bs[kk][tx * 4];
            float a[4] = {av.x, av.y, av.z, av.w};
            float b[4] = {bv.x, bv.y, bv.z, bv.w};
#pragma unroll
            for (int i = 0; i < 4; i++)
#pragma unroll
                for (int u = 0; u < 4; u++) acc[i][u] = fmaf(a[i], b[u], acc[i][u]);
        }
        __syncthreads();
    }
#pragma unroll
    for (int i = 0; i < 4; i++) {
        float4 v = make_float4(acc[i][0], acc[i][1], acc[i][2], acc[i][3]);
        *(float4*)&g_Wx[(m0 + ty * 4 + i) * 1024 + n0 + tx * 4] = v;
    }
}

// ---------------- init states from init_h / init_c ----------------
__global__ void init_state_kernel(const float* __restrict__ ih, const float* __restrict__ ic) {
    int idx = blockIdx.x * blockDim.x + threadIdx.x;
    if (idx >= GD * NN * DIMM) return;
    int j  = idx & (DIMM - 1);
    int gd = idx / (NN * DIMM);
    int r  = idx % (NN * DIMM);
    g_H[0][gd][r] = ih[gd * DIMM + j];
    g_C[gd][r]    = ic[gd * DIMM + j];
}

// ---------------- fused recurrent step ----------------
// z = [h_child(t,dir), h_state] (512) @ [kernel;rec] (512x1024) + bias, then LSTM pointwise.
// grid: (32 Mtiles of 128, 8 dim-tiles of 32, 8 gate*dir). Active rows are prefix [0, cnt[t]).
__global__ __launch_bounds__(256, 2) void step_kernel(
    int t,
    const float* __restrict__ h_tensor, const int* __restrict__ indice,
    const float* __restrict__ lk, const float* __restrict__ lr, const float* __restrict__ lb) {
    const int gd = blockIdx.z;
    const int Mact = g_cnt[t];
    const int m0 = blockIdx.x * 128;
    if (m0 >= Mact) return;
    const int cn = blockIdx.y;          // hidden dims [cn*32, cn*32+32)
    const int tid = threadIdx.x;
    const int tx = tid & 15, ty = tid >> 4;

    __shared__ __align__(16) float As[32][132];
    __shared__ __align__(16) float Bs[32][128];
    __shared__ int childIdx[128];

    if (tid < 128) {
        int s = m0 + tid;
        int ci = 0;
        if (s < Mact) {
            int orig = g_sorted_orig[s];
            int len  = g_sorted_len[s];
            int tt = (gd & 1) ? (len - 1 - t) : t;   // bwd uses reversed valid prefix
            ci = indice[orig * KK + tt];
        }
        childIdx[tid] = ci;
    }

    const float* Wk = lk + (size_t)gd * 256 * 1024;
    const float* Wr = lr + (size_t)gd * 256 * 1024;
    const float* Hin  = &g_H[t & 1][gd][0];
    float*       Hout = &g_H[(t + 1) & 1][gd][0];
    float*       Cst  = &g_C[gd][0];

    float acc[8][8];
#pragma unroll
    for (int gg = 0; gg < 4; gg++) {
        float b0 = lb[gd * 1024 + gg * 256 + cn * 32 + tx * 2 + 0];
        float b1 = lb[gd * 1024 + gg * 256 + cn * 32 + tx * 2 + 1];
#pragma unroll
        for (int i = 0; i < 8; i++) { acc[i][gg * 2 + 0] = b0; acc[i][gg * 2 + 1] = b1; }
    }
    __syncthreads();

    for (int kb = 0; kb < 16; kb++) {
        int k0 = kb * 32;
#pragma unroll
        for (int j = 0; j < 4; j++) {           // A: 128 rows x 32 k (gathered)
            int l = tid + 256 * j;
            int row = l >> 3;
            int kp  = (l & 7) * 4;
            const float* src = (k0 < 256)
                ? (h_tensor + (size_t)childIdx[row] * 256 + k0 + kp)
                : (Hin + (size_t)(m0 + row) * 256 + (k0 - 256) + kp);
            float4 v = *(const float4*)src;
            As[kp + 0][row] = v.x; As[kp + 1][row] = v.y;
            As[kp + 2][row] = v.z; As[kp + 3][row] = v.w;
        }
#pragma unroll
        for (int j = 0; j < 4; j++) {           // B: 32 k x 128 cols (4 gates x 32 dims)
            int l = tid + 256 * j;
            int k = l >> 5;
            int cf4 = l & 31;
            int c = cf4 * 4;
            int gate = c >> 5; int qq = c & 31;
            int kg = k0 + k;
            const float* wsrc = (kg < 256) ? (Wk + (size_t)kg * 1024)
                                           : (Wr + (size_t)(kg - 256) * 1024);
            float4 v = *(const float4*)(wsrc + gate * 256 + cn * 32 + qq);
            *(float4*)&Bs[k][c] = v;
        }
        __syncthreads();
#pragma unroll
        for (int kk = 0; kk < 32; kk++) {
            float a[8];
            float4 a0 = *(const float4*)&As[kk][ty * 8];
            float4 a1 = *(const float4*)&As[kk][ty * 8 + 4];
            a[0] = a0.x; a[1] = a0.y; a[2] = a0.z; a[3] = a0.w;
            a[4] = a1.x; a[5] = a1.y; a[6] = a1.z; a[7] = a1.w;
            float b[8];
#pragma unroll
            for (int gg = 0; gg < 4; gg++) {
                float2 bv = *(const float2*)&Bs[kk][gg * 32 + tx * 2];
                b[gg * 2] = bv.x; b[gg * 2 + 1] = bv.y;
            }
#pragma unroll
            for (int i = 0; i < 8; i++)
#pragma unroll
                for (int c8 = 0; c8 < 8; c8++) acc[i][c8] = fmaf(a[i], b[c8], acc[i][c8]);
        }
        __syncthreads();
    }

    // pointwise LSTM update (z split order: i, f, g(u), o)
    const int d = gd & 1;
    const bool isG0 = (gd < 2);
#pragma unroll
    for (int i = 0; i < 8; i++) {
        int s = m0 + ty * 8 + i;
        if (s < Mact) {
            int dim = cn * 32 + tx * 2;
            int off = s * DIMM + dim;
            float2 cold = *(float2*)&Cst[off];
            float2 cn2, hn2;
            {
                float zi = acc[i][0], zf = acc[i][2], zu = acc[i][4], zo = acc[i][6];
                float c0 = sigm(zf) * cold.x + sigm(zi) * tanhf(zu);
                cn2.x = c0; hn2.x = sigm(zo) * tanhf(c0);
            }
            {
                float zi = acc[i][1], zf = acc[i][3], zu = acc[i][5], zo = acc[i][7];
                float c1 = sigm(zf) * cold.y + sigm(zi) * tanhf(zu);
                cn2.y = c1; hn2.y = sigm(zo) * tanhf(c1);
            }
            *(float2*)&Cst[off]  = cn2;
            *(float2*)&Hout[off] = hn2;
            if (isG0) *(float2*)&g_Yseq[d][(s * KK + t) * DIMM + dim] = hn2;
        }
    }
}

// ---------------- final combine: fc projections + gate math ----------------
__global__ __launch_bounds__(256) void final_kernel(
    const float* __restrict__ c_tensor, const int* __restrict__ indice,
    const float* __restrict__ fc_w, float* __restrict__ out) {
    int s = blockIdx.x;
    int j = threadIdx.x;
    int orig = g_sorted_orig[s];
    int len  = g_sorted_len[s];
    int par  = len & 1;   // final h-state buffer

    __shared__ float ysm[16][512];
    __shared__ float fcs[8][256];

    // load concat(y_f[t], y_b[t]) rows; zero rows t >= len
    for (int idx = j; idx < 16 * 512; idx += 256) {
        int t = idx >> 9;
        int m = idx & 511;
        float v = 0.f;
        if (t < len) {
            v = (m < 256) ? g_Yseq[0][(s * KK + t) * DIMM + m]
                          : g_Yseq[1][(s * KK + t) * DIMM + (m - 256)];
        }
        ysm[t][m] = v;
    }
    __syncthreads();

    // f_seq[t][j] = ycat_t . fc_w[0][:,j], chunked over m so fc_w[0] is read once per CTA
    float acc[16];
#pragma unroll
    for (int t = 0; t < 16; t++) acc[t] = 0.f;
    for (int mc = 0; mc < 64; mc++) {
        int m0 = mc * 8;
#pragma unroll
        for (int it = 0; it < 8; it++) fcs[it][j] = fc_w[(m0 + it) * 256 + j];
        __syncthreads();
#pragma unroll
        for (int mm = 0; mm < 8; mm++) {
            float b = fcs[mm][j];
#pragma unroll
            for (int t = 0; t < 16; t++) acc[t] = fmaf(ysm[t][m0 + mm], b, acc[t]);
        }
        __syncthreads();
    }

    // branch_f = sum_{t<len} sigmoid(W_f_x + f_seq[t]) * c_child[t]
    float Wf = g_Wx[orig * 1024 + j];
    float bf = 0.f;
#pragma unroll
    for (int t = 0; t < 16; t++) {
        if (t < len) {
            int ci = indice[orig * KK + t];
            bf += sigm(Wf + acc[t]) * c_tensor[(size_t)ci * DIMM + j];
        }
    }

    // gates 1..3: y_last = concat(final fwd h, final bwd h) @ fc_w[g]
    float dots[3];
#pragma unroll
    for (int g = 1; g <= 3; g++) {
        __syncthreads();
        for (int idx = j; idx < 512; idx += 256) {
            int dsel = idx >> 8; int m = idx & 255;
            ysm[0][idx] = g_H[par][g * 2 + dsel][s * DIMM + m];
        }
        __syncthreads();
        float dot = 0.f;
        for (int m = 0; m < 512; m++)
            dot = fmaf(ysm[0][m], fc_w[(g * 512 + m) * 256 + j], dot);
        dots[g - 1] = dot;
    }

    float Wi = g_Wx[orig * 1024 + 256 + j];
    float Wu = g_Wx[orig * 1024 + 512 + j];
    float Wo = g_Wx[orig * 1024 + 768 + j];
    float bi = sigm(dots[0] + Wi);
    float bu = tanhf(dots[1] + Wu);
    float bo = sigm(dots[2] + Wo);
    float nc = bi * bu + bf;
    float nh = bo * tanhf(nc);
    out[(size_t)orig * DIMM + j] = nh;
    out[(size_t)NN * DIMM + (size_t)orig * DIMM + j] = nc;
}

// ---------------- launch ----------------
extern "C" void kernel_launch(void* const* d_in, const int* in_sizes, int n_in,
                              void* d_out, int out_size) {
    const float* x        = (const float*)d_in[0];
    const float* h_tensor = (const float*)d_in[1];
    const float* c_tensor = (const float*)d_in[2];
    const int*   indice   = (const int*)d_in[3];
    const float* W_w      = (const float*)d_in[4];
    const float* W_b      = (const float*)d_in[5];
    const float* lk       = (const float*)d_in[6];
    const float* lr       = (const float*)d_in[7];
    const float* lb       = (const float*)d_in[8];
    const float* ih       = (const float*)d_in[9];
    const float* ic       = (const float*)d_in[10];
    const float* fc       = (const float*)d_in[11];
    float* out = (float*)d_out;

    zero_hist_kernel<<<1, 32>>>();
    len_hist_kernel<<<NN / 256, 256>>>(indice);
    prefix_kernel<<<1, 1>>>();
    scatter_kernel<<<NN / 256, 256>>>(indice);
    wx_gemm_kernel<<<dim3(64, 16), 256>>>(x, W_w, W_b);
    init_state_kernel<<<(GD * NN * DIMM) / 256, 256>>>(ih, ic);
    for (int t = 0; t < 16; t++)
        step_kernel<<<dim3(32, 8, 8), 256>>>(t, h_tensor, indice, lk, lr, lb);
    final_kernel<<<NN, 256>>>(c_tensor, indice, fc, out);
}

// round 2
// speedup vs baseline: 1.0868x; 1.0868x over previous
#include <cuda_runtime.h>
#include <math.h>

#define NN   4096
#define KK   16
#define DIMM 256
#define RR   8192
#define GD   8

// ---- device scratch (static, no allocation) ----
__device__ int   g_hist[17];
__device__ int   g_off[17];
__device__ int   g_cnt[16];
__device__ int   g_sorted_orig[NN];
__device__ int   g_sorted_len[NN];
__device__ float g_Wx[NN * 1024];
__device__ float g_H[2][GD][NN * DIMM];   // double-buffered h state
__device__ float g_C[GD][NN * DIMM];      // c state (element-owned, no race)
__device__ float g_Yseq[2][NN * KK * DIMM]; // gate-0 (f) fwd/bwd sequence outputs

__device__ __forceinline__ float sigm(float x) { return 1.f / (1.f + expf(-x)); }

// ---- packed f32x2 helpers (FFMA2: 2 FP32 FMA per issue, PTX-only) ----
__device__ __forceinline__ void ffma2(unsigned long long& d, unsigned long long a,
                                      unsigned long long b) {
    asm("fma.rn.f32x2 %0, %1, %2, %0;" : "+l"(d) : "l"(a), "l"(b));
}
__device__ __forceinline__ unsigned long long dup2(float x) {
    unsigned long long r;
    asm("mov.b64 %0, {%1, %1};" : "=l"(r) : "f"(x));
    return r;
}
__device__ __forceinline__ unsigned long long pack2(float lo, float hi) {
    unsigned long long r;
    asm("mov.b64 %0, {%1, %2};" : "=l"(r) : "f"(lo), "f"(hi));
    return r;
}
__device__ __forceinline__ void unpack2(unsigned long long v, float& lo, float& hi) {
    asm("mov.b64 {%0, %1}, %2;" : "=f"(lo), "=f"(hi) : "l"(v));
}

// ---------------- sorting by length (desc) ----------------
__global__ void zero_hist_kernel() {
    if (threadIdx.x < 17) g_hist[threadIdx.x] = 0;
}

__global__ void len_hist_kernel(const int* __restrict__ indice) {
    int n = blockIdx.x * blockDim.x + threadIdx.x;
    if (n >= NN) return;
    int len = 0;
#pragma unroll
    for (int k = 0; k < KK; k++) len += (indice[n * KK + k] != -1);
    atomicAdd(&g_hist[len], 1);
}

__global__ void prefix_kernel() {
    if (threadIdx.x != 0 || blockIdx.x != 0) return;
    int run = 0;
    for (int l = 16; l >= 1; l--) { g_off[l] = run; run += g_hist[l]; }
    for (int t = 0; t < 16; t++) g_cnt[t] = g_off[t + 1] + g_hist[t + 1]; // #nodes with len > t
}

__global__ void scatter_kernel(const int* __restrict__ indice) {
    int n = blockIdx.x * blockDim.x + threadIdx.x;
    if (n >= NN) return;
    int len = 0;
#pragma unroll
    for (int k = 0; k < KK; k++) len += (indice[n * KK + k] != -1);
    int pos = atomicAdd(&g_off[len], 1);
    g_sorted_orig[pos] = n;
    g_sorted_len[pos]  = len;
}

// ---------------- W_x = x @ W_w + W_b  ([4096,256]@[256,1024]) ----------------
__global__ __launch_bounds__(256) void wx_gemm_kernel(
    const float* __restrict__ A, const float* __restrict__ B, const float* __restrict__ bias) {
    int m0 = blockIdx.x * 64, n0 = blockIdx.y * 64;
    int tid = threadIdx.x, tx = tid & 15, ty = tid >> 4;
    __shared__ __align__(16) float As[32][68];
    __shared__ __align__(16) float Bs[32][64];
    float acc[4][4];
#pragma unroll
    for (int u = 0; u < 4; u++) {
        float b = bias[n0 + tx * 4 + u];
#pragma unroll
        for (int i = 0; i < 4; i++) acc[i][u] = b;
    }
    for (int kb = 0; kb < 8; kb++) {
        int k0 = kb * 32;
        {   // A tile 64x32
            int row = tid >> 2; int kp = (tid & 3) * 8;
            float4 v0 = *(const float4*)(A + (m0 + row) * 256 + k0 + kp);
            float4 v1 = *(const float4*)(A + (m0 + row) * 256 + k0 + kp + 4);
            As[kp + 0][row] = v0.x; As[kp + 1][row] = v0.y; As[kp + 2][row] = v0.z; As[kp + 3][row] = v0.w;
            As[kp + 4][row] = v1.x; As[kp + 5][row] = v1.y; As[kp + 6][row] = v1.z; As[kp + 7][row] = v1.w;
        }
#pragma unroll
        for (int jj = 0; jj < 8; jj++) { // B tile 32x64
            int l = tid + 256 * jj; int k = l >> 6; int c = l & 63;
            Bs[k][c] = B[(k0 + k) * 1024 + n0 + c];
        }
        __syncthreads();
#pragma unroll
        for (int kk = 0; kk < 32; kk++) {
            float4 av = *(const float4*)&As[kk][ty * 4];
            float4 bv = *(const float4*)&Bs[kk][tx * 4];
            float a[4] = {av.x, av.y, av.z, av.w};
            float b[4] = {bv.x, bv.y, bv.z, bv.w};
#pragma unroll
            for (int i = 0; i < 4; i++)
#pragma unroll
                for (int u = 0; u < 4; u++) acc[i][u] = fmaf(a[i], b[u], acc[i][u]);
        }
        __syncthreads();
    }
#pragma unroll
    for (int i = 0; i < 4; i++) {
        float4 v = make_float4(acc[i][0], acc[i][1], acc[i][2], acc[i][3]);
        *(float4*)&g_Wx[(m0 + ty * 4 + i) * 1024 + n0 + tx * 4] = v;
    }
}

// ---------------- init states from init_h / init_c ----------------
__global__ void init_state_kernel(const float* __restrict__ ih, const float* __restrict__ ic) {
    int idx = blockIdx.x * blockDim.x + threadIdx.x;
    if (idx >= GD * NN * DIMM) return;
    int j  = idx & (DIMM - 1);
    int gd = idx / (NN * DIMM);
    int r  = idx % (NN * DIMM);
    g_H[0][gd][r] = ih[gd * DIMM + j];
    g_C[gd][r]    = ic[gd * DIMM + j];
}

// ---------------- fused recurrent step ----------------
// z = [h_child(t,dir), h_state] (512) @ [kernel;rec] (512x1024) + bias, then LSTM pointwise.
// grid: (32 Mtiles of 128, 8 dim-tiles of 32, 8 gate*dir). Active rows are prefix [0, cnt[t]).
// Inner product uses packed fma.rn.f32x2 (FFMA2) -> 2 FP32 FMA per fma-pipe issue.
__global__ __launch_bounds__(256, 2) void step_kernel(
    int t,
    const float* __restrict__ h_tensor, const int* __restrict__ indice,
    const float* __restrict__ lk, const float* __restrict__ lr, const float* __restrict__ lb) {
    const int gd = blockIdx.z;
    const int Mact = g_cnt[t];
    const int m0 = blockIdx.x * 128;
    if (m0 >= Mact) return;
    const int cn = blockIdx.y;          // hidden dims [cn*32, cn*32+32)
    const int tid = threadIdx.x;
    const int tx = tid & 15, ty = tid >> 4;

    __shared__ __align__(16) float As[32][132];
    __shared__ __align__(16) float Bs[32][128];
    __shared__ int childIdx[128];

    if (tid < 128) {
        int s = m0 + tid;
        int ci = 0;
        if (s < Mact) {
            int orig = g_sorted_orig[s];
            int len  = g_sorted_len[s];
            int tt = (gd & 1) ? (len - 1 - t) : t;   // bwd uses reversed valid prefix
            ci = indice[orig * KK + tt];
        }
        childIdx[tid] = ci;
    }

    const float* Wk = lk + (size_t)gd * 256 * 1024;
    const float* Wr = lr + (size_t)gd * 256 * 1024;
    const float* Hin  = &g_H[t & 1][gd][0];
    float*       Hout = &g_H[(t + 1) & 1][gd][0];
    float*       Cst  = &g_C[gd][0];

    // acc2[i][gg] packs output columns (gg gate, dims tx*2, tx*2+1)
    unsigned long long acc2[8][4];
#pragma unroll
    for (int gg = 0; gg < 4; gg++) {
        float b0 = lb[gd * 1024 + gg * 256 + cn * 32 + tx * 2 + 0];
        float b1 = lb[gd * 1024 + gg * 256 + cn * 32 + tx * 2 + 1];
        unsigned long long bp = pack2(b0, b1);
#pragma unroll
        for (int i = 0; i < 8; i++) acc2[i][gg] = bp;
    }
    __syncthreads();

    for (int kb = 0; kb < 16; kb++) {
        int k0 = kb * 32;
#pragma unroll
        for (int j = 0; j < 4; j++) {           // A: 128 rows x 32 k (gathered)
            int l = tid + 256 * j;
            int row = l >> 3;
            int kp  = (l & 7) * 4;
            const float* src = (k0 < 256)
                ? (h_tensor + (size_t)childIdx[row] * 256 + k0 + kp)
                : (Hin + (size_t)(m0 + row) * 256 + (k0 - 256) + kp);
            float4 v = *(const float4*)src;
            As[kp + 0][row] = v.x; As[kp + 1][row] = v.y;
            As[kp + 2][row] = v.z; As[kp + 3][row] = v.w;
        }
#pragma unroll
        for (int j = 0; j < 4; j++) {           // B: 32 k x 128 cols (4 gates x 32 dims)
            int l = tid + 256 * j;
            int k = l >> 5;
            int cf4 = l & 31;
            int c = cf4 * 4;
            int gate = c >> 5; int qq = c & 31;
            int kg = k0 + k;
            const float* wsrc = (kg < 256) ? (Wk + (size_t)kg * 1024)
                                           : (Wr + (size_t)(kg - 256) * 1024);
            float4 v = *(const float4*)(wsrc + gate * 256 + cn * 32 + qq);
            *(float4*)&Bs[k][c] = v;
        }
        __syncthreads();
#pragma unroll
        for (int kk = 0; kk < 32; kk++) {
            float a[8];
            float4 a0 = *(const float4*)&As[kk][ty * 8];
            float4 a1 = *(const float4*)&As[kk][ty * 8 + 4];
            a[0] = a0.x; a[1] = a0.y; a[2] = a0.z; a[3] = a0.w;
            a[4] = a1.x; a[5] = a1.y; a[6] = a1.z; a[7] = a1.w;
            unsigned long long bv[4];
#pragma unroll
            for (int gg = 0; gg < 4; gg++)
                bv[gg] = *(const unsigned long long*)&Bs[kk][gg * 32 + tx * 2];
#pragma unroll
            for (int i = 0; i < 8; i++) {
                unsigned long long ad = dup2(a[i]);
#pragma unroll
                for (int gg = 0; gg < 4; gg++) ffma2(acc2[i][gg], ad, bv[gg]);
            }
        }
        __syncthreads();
    }

    // pointwise LSTM update (z split order: i, f, g(u), o)
    const int d = gd & 1;
    const bool isG0 = (gd < 2);
#pragma unroll
    for (int i = 0; i < 8; i++) {
        int s = m0 + ty * 8 + i;
        if (s < Mact) {
            int dim = cn * 32 + tx * 2;
            int off = s * DIMM + dim;
            float2 cold = *(float2*)&Cst[off];
            float zi0, zi1, zf0, zf1, zu0, zu1, zo0, zo1;
            unpack2(acc2[i][0], zi0, zi1);
            unpack2(acc2[i][1], zf0, zf1);
            unpack2(acc2[i][2], zu0, zu1);
            unpack2(acc2[i][3], zo0, zo1);
            float2 cn2, hn2;
            {
                float c0 = sigm(zf0) * cold.x + sigm(zi0) * tanhf(zu0);
                cn2.x = c0; hn2.x = sigm(zo0) * tanhf(c0);
            }
            {
                float c1 = sigm(zf1) * cold.y + sigm(zi1) * tanhf(zu1);
                cn2.y = c1; hn2.y = sigm(zo1) * tanhf(c1);
            }
            *(float2*)&Cst[off]  = cn2;
            *(float2*)&Hout[off] = hn2;
            if (isG0) *(float2*)&g_Yseq[d][(s * KK + t) * DIMM + dim] = hn2;
        }
    }
}

// ---------------- final combine: fc projections + gate math ----------------
__global__ __launch_bounds__(256) void final_kernel(
    const float* __restrict__ c_tensor, const int* __restrict__ indice,
    const float* __restrict__ fc_w, float* __restrict__ out) {
    int s = blockIdx.x;
    int j = threadIdx.x;
    int orig = g_sorted_orig[s];
    int len  = g_sorted_len[s];
    int par  = len & 1;   // final h-state buffer

    __shared__ float ysm[16][512];
    __shared__ float fcs[8][256];

    // load concat(y_f[t], y_b[t]) rows; zero rows t >= len
    for (int idx = j; idx < 16 * 512; idx += 256) {
        int t = idx >> 9;
        int m = idx & 511;
        float v = 0.f;
        if (t < len) {
            v = (m < 256) ? g_Yseq[0][(s * KK + t) * DIMM + m]
                          : g_Yseq[1][(s * KK + t) * DIMM + (m - 256)];
        }
        ysm[t][m] = v;
    }
    __syncthreads();

    // f_seq[t][j] = ycat_t . fc_w[0][:,j], chunked over m so fc_w[0] is read once per CTA
    float acc[16];
#pragma unroll
    for (int t = 0; t < 16; t++) acc[t] = 0.f;
    for (int mc = 0; mc < 64; mc++) {
        int m0 = mc * 8;
#pragma unroll
        for (int it = 0; it < 8; it++) fcs[it][j] = fc_w[(m0 + it) * 256 + j];
        __syncthreads();
#pragma unroll
        for (int mm = 0; mm < 8; mm++) {
            float b = fcs[mm][j];
#pragma unroll
            for (int t = 0; t < 16; t++) acc[t] = fmaf(ysm[t][m0 + mm], b, acc[t]);
        }
        __syncthreads();
    }

    // branch_f = sum_{t<len} sigmoid(W_f_x + f_seq[t]) * c_child[t]
    float Wf = g_Wx[orig * 1024 + j];
    float bf = 0.f;
#pragma unroll
    for (int t = 0; t < 16; t++) {
        if (t < len) {
            int ci = indice[orig * KK + t];
            bf += sigm(Wf + acc[t]) * c_tensor[(size_t)ci * DIMM + j];
        }
    }

    // gates 1..3: y_last = concat(final fwd h, final bwd h) @ fc_w[g]
    float dots[3];
#pragma unroll
    for (int g = 1; g <= 3; g++) {
        __syncthreads();
        for (int idx = j; idx < 512; idx += 256) {
            int dsel = idx >> 8; int m = idx & 255;
            ysm[0][idx] = g_H[par][g * 2 + dsel][s * DIMM + m];
        }
        __syncthreads();
        float dot = 0.f;
        for (int m = 0; m < 512; m++)
            dot = fmaf(ysm[0][m], fc_w[(g * 512 + m) * 256 + j], dot);
        dots[g - 1] = dot;
    }

    float Wi = g_Wx[orig * 1024 + 256 + j];
    float Wu = g_Wx[orig * 1024 + 512 + j];
    float Wo = g_Wx[orig * 1024 + 768 + j];
    float bi = sigm(dots[0] + Wi);
    float bu = tanhf(dots[1] + Wu);
    float bo = sigm(dots[2] + Wo);
    float nc = bi * bu + bf;
    float nh = bo * tanhf(nc);
    out[(size_t)orig * DIMM + j] = nh;
    out[(size_t)NN * DIMM + (size_t)orig * DIMM + j] = nc;
}

// ---------------- launch ----------------
extern "C" void kernel_launch(void* const* d_in, const int* in_sizes, int n_in,
                              void* d_out, int out_size) {
    const float* x        = (const float*)d_in[0];
    const float* h_tensor = (const float*)d_in[1];
    const float* c_tensor = (const float*)d_in[2];
    const int*   indice   = (const int*)d_in[3];
    const float* W_w      = (const float*)d_in[4];
    const float* W_b      = (const float*)d_in[5];
    const float* lk       = (const float*)d_in[6];
    const float* lr       = (const float*)d_in[7];
    const float* lb       = (const float*)d_in[8];
    const float* ih       = (const float*)d_in[9];
    const float* ic       = (const float*)d_in[10];
    const float* fc       = (const float*)d_in[11];
    float* out = (float*)d_out;

    zero_hist_kernel<<<1, 32>>>();
    len_hist_kernel<<<NN / 256, 256>>>(indice);
    prefix_kernel<<<1, 1>>>();
    scatter_kernel<<<NN / 256, 256>>>(indice);
    wx_gemm_kernel<<<dim3(64, 16), 256>>>(x, W_w, W_b);
    init_state_kernel<<<(GD * NN * DIMM) / 256, 256>>>(ih, ic);
    for (int t = 0; t < 16; t++)
        step_kernel<<<dim3(32, 8, 8), 256>>>(t, h_tensor, indice, lk, lr, lb);
    final_kernel<<<NN, 256>>>(c_tensor, indice, fc, out);
}

// round 4
// speedup vs baseline: 1.5890x; 1.4621x over previous
#include <cuda_runtime.h>
#include <cuda_bf16.h>
#include <math.h>
#include <cstdint>

#define NN   4096
#define KK   16
#define DIMM 256
#define RR   8192
#define GD   8

// ---- device scratch (static, no allocation) ----
__device__ int   g_hist[17];
__device__ int   g_off[17];
__device__ int   g_cnt[16];
__device__ int   g_sorted_orig[NN];
__device__ int   g_sorted_len[NN];
__device__ float g_Wx[NN * 1024];
__device__ float g_C[GD][NN * DIMM];        // c state fp32
__device__ float g_Yseq[2][NN * KK * DIMM]; // gate-0 (f) fwd/bwd sequence outputs
// split bf16 h/H state + weights
__device__ __nv_bfloat16 g_hsp0[RR * DIMM];          // h_tensor hi
__device__ __nv_bfloat16 g_hsp1[RR * DIMM];          // h_tensor lo
__device__ __nv_bfloat16 g_Hh[2][GD][NN * DIMM];     // H state hi (double buffered)
__device__ __nv_bfloat16 g_Hl[2][GD][NN * DIMM];     // H state lo
// packed weights: [gd][ntile8][chunk8] blocks of 128 n-rows x 64 k halves (K-major BT)
__device__ __nv_bfloat16 g_Bp0[8u * 8u * 8u * 8192u]; // hi
__device__ __nv_bfloat16 g_Bp1[8u * 8u * 8u * 8192u]; // lo

__device__ __forceinline__ float sigm(float x) { return 1.f / (1.f + expf(-x)); }

__device__ __forceinline__ void bsplit(float v, __nv_bfloat16& h, __nv_bfloat16& l) {
    h = __float2bfloat16(v);
    l = __float2bfloat16(v - __bfloat162float(h));
}

// ---- PTX helpers (non-'a' features only: cp.async, ldmatrix, mma.sync) ----
__device__ __forceinline__ uint32_t smem_u32(const void* p) {
    uint32_t a;
    asm("{ .reg .u64 t; cvta.to.shared.u64 t, %1; cvt.u32.u64 %0, t; }" : "=r"(a) : "l"(p));
    return a;
}
#define CP_ASYNC16(dst, src) \
    asm volatile("cp.async.cg.shared.global [%0], [%1], 16;" :: "r"(dst), "l"(src))
#define CP_COMMIT() asm volatile("cp.async.commit_group;" ::: "memory")
#define CP_WAIT(n)  asm volatile("cp.async.wait_group %0;" :: "n"(n) : "memory")

__device__ __forceinline__ void ldsm4(uint32_t* r, uint32_t addr) {
    asm volatile("ldmatrix.sync.aligned.m8n8.x4.shared.b16 {%0,%1,%2,%3}, [%4];"
                 : "=r"(r[0]), "=r"(r[1]), "=r"(r[2]), "=r"(r[3]) : "r"(addr));
}
__device__ __forceinline__ void mma_bf16(float* c, const uint32_t* a, const uint32_t* b) {
    asm volatile("mma.sync.aligned.m16n8k16.row.col.f32.bf16.bf16.f32 "
                 "{%0,%1,%2,%3}, {%4,%5,%6,%7}, {%8,%9}, {%0,%1,%2,%3};"
                 : "+f"(c[0]), "+f"(c[1]), "+f"(c[2]), "+f"(c[3])
                 : "r"(a[0]), "r"(a[1]), "r"(a[2]), "r"(a[3]), "r"(b[0]), "r"(b[1]));
}

// ---------------- sorting by length (desc) ----------------
__global__ void zero_hist_kernel() { if (threadIdx.x < 17) g_hist[threadIdx.x] = 0; }

__global__ void len_hist_kernel(const int* __restrict__ indice) {
    int n = blockIdx.x * blockDim.x + threadIdx.x;
    if (n >= NN) return;
    int len = 0;
#pragma unroll
    for (int k = 0; k < KK; k++) len += (indice[n * KK + k] != -1);
    atomicAdd(&g_hist[len], 1);
}

__global__ void prefix_kernel() {
    if (threadIdx.x != 0 || blockIdx.x != 0) return;
    int run = 0;
    for (int l = 16; l >= 1; l--) { g_off[l] = run; run += g_hist[l]; }
    for (int t = 0; t < 16; t++) g_cnt[t] = g_off[t + 1] + g_hist[t + 1];
}

__global__ void scatter_kernel(const int* __restrict__ indice) {
    int n = blockIdx.x * blockDim.x + threadIdx.x;
    if (n >= NN) return;
    int len = 0;
#pragma unroll
    for (int k = 0; k < KK; k++) len += (indice[n * KK + k] != -1);
    int pos = atomicAdd(&g_off[len], 1);
    g_sorted_orig[pos] = n;
    g_sorted_len[pos]  = len;
}

// ------- prep: split h_tensor, pack/split weights, init states -------
__global__ void prep_kernel(const float* __restrict__ ih, const float* __restrict__ ic,
                            const float* __restrict__ lk, const float* __restrict__ lr,
                            const float* __restrict__ h_tensor) {
    int idx = blockIdx.x * blockDim.x + threadIdx.x;
    if (idx < RR * DIMM) {           // h_tensor split
        bsplit(h_tensor[idx], g_hsp0[idx], g_hsp1[idx]);
    }
    if (idx < 8 * 512 * 1024) {      // weight pack: gate-interleaved, K-major BT blocks
        int gd = idx >> 19;
        int rem = idx & ((1 << 19) - 1);
        int kg = rem >> 10;          // 0..511
        int pc = rem & 1023;         // packed col: 4*j + q (q: 0=i,1=f,2=u,3=o)
        int oc = (pc & 3) * 256 + (pc >> 2);
        float w = (kg < 256) ? lk[((size_t)gd * 256 + kg) * 1024 + oc]
                             : lr[((size_t)gd * 256 + (kg - 256)) * 1024 + oc];
        int ntile = pc >> 7;         // 8 tiles of 128 packed cols
        int n     = pc & 127;
        int chunk = kg >> 6;
        int k     = kg & 63;
        size_t dst = ((size_t)(gd * 8 + ntile) * 8 + chunk) * 8192u + (size_t)n * 64 + k;
        bsplit(w, g_Bp0[dst], g_Bp1[dst]);
    }
    if (idx < GD * NN * DIMM) {      // init H (split) + C
        int j  = idx & (DIMM - 1);
        int gd = idx / (NN * DIMM);
        int r  = idx % (NN * DIMM);
        bsplit(ih[gd * DIMM + j], g_Hh[0][gd][r], g_Hl[0][gd][r]);
        g_C[gd][r] = ic[gd * DIMM + j];
    }
}

// ---------------- W_x = x @ W_w + W_b ----------------
__global__ __launch_bounds__(256) void wx_gemm_kernel(
    const float* __restrict__ A, const float* __restrict__ B, const float* __restrict__ bias) {
    int m0 = blockIdx.x * 64, n0 = blockIdx.y * 64;
    int tid = threadIdx.x, tx = tid & 15, ty = tid >> 4;
    __shared__ __align__(16) float As[32][68];
    __shared__ __align__(16) float Bs[32][64];
    float acc[4][4];
#pragma unroll
    for (int u = 0; u < 4; u++) {
        float b = bias[n0 + tx * 4 + u];
#pragma unroll
        for (int i = 0; i < 4; i++) acc[i][u] = b;
    }
    for (int kb = 0; kb < 8; kb++) {
        int k0 = kb * 32;
        {
            int row = tid >> 2; int kp = (tid & 3) * 8;
            float4 v0 = *(const float4*)(A + (m0 + row) * 256 + k0 + kp);
            float4 v1 = *(const float4*)(A + (m0 + row) * 256 + k0 + kp + 4);
            As[kp + 0][row] = v0.x; As[kp + 1][row] = v0.y; As[kp + 2][row] = v0.z; As[kp + 3][row] = v0.w;
            As[kp + 4][row] = v1.x; As[kp + 5][row] = v1.y; As[kp + 6][row] = v1.z; As[kp + 7][row] = v1.w;
        }
#pragma unroll
        for (int jj = 0; jj < 8; jj++) {
            int l = tid + 256 * jj; int k = l >> 6; int c = l & 63;
            Bs[k][c] = B[(k0 + k) * 1024 + n0 + c];
        }
        __syncthreads();
#pragma unroll
        for (int kk = 0; kk < 32; kk++) {
            float4 av = *(const float4*)&As[kk][ty * 4];
            float4 bv = *(const float4*)&Bs[kk][tx * 4];
            float a[4] = {av.x, av.y, av.z, av.w};
            float b[4] = {bv.x, bv.y, bv.z, bv.w};
#pragma unroll
            for (int i = 0; i < 4; i++)
#pragma unroll
                for (int u = 0; u < 4; u++) acc[i][u] = fmaf(a[i], b[u], acc[i][u]);
        }
        __syncthreads();
    }
#pragma unroll
    for (int i = 0; i < 4; i++) {
        float4 v = make_float4(acc[i][0], acc[i][1], acc[i][2], acc[i][3]);
        *(float4*)&g_Wx[(m0 + ty * 4 + i) * 1024 + n0 + tx * 4] = v;
    }
}

// ---------------- HMMA recurrent step ----------------
// smem: 2 buffers x [Ah | Al | Bh | Bl], each split = 128 rows x 72 halves (pad) = 18432B
#define SPLIT_B   18432
#define BUF_B     (4 * SPLIT_B)            // 73728
#define SM_CHILD  (2 * BUF_B)              // 147456
#define SMEM_STEP (2 * BUF_B + 512)        // 147968

__global__ __launch_bounds__(256, 1) void step_mma_kernel(
    int t, const int* __restrict__ indice, const float* __restrict__ lb) {
    extern __shared__ __align__(1024) char smem[];
    const int gd = blockIdx.z;
    const int ntile = blockIdx.y;
    const int Mact = g_cnt[t];
    const int m0 = blockIdx.x * 128;
    if (m0 >= Mact) return;
    const int tid = threadIdx.x;
    const int wid = tid >> 5, lane = tid & 31;
    const uint32_t sb = smem_u32(smem);
    int* childs = (int*)(smem + SM_CHILD);

    if (tid < 128) {
        int s = m0 + tid;
        int ci = 0;
        if (s < Mact) {
            int orig = g_sorted_orig[s];
            int len  = g_sorted_len[s];
            int tt = (gd & 1) ? (len - 1 - t) : t;
            ci = indice[orig * KK + tt];
        }
        childs[tid] = ci;
    }
    __syncthreads();

    const __nv_bfloat16* Hh_in = &g_Hh[t & 1][gd][0];
    const __nv_bfloat16* Hl_in = &g_Hl[t & 1][gd][0];
    const size_t bblk = (size_t)(gd * 8 + ntile) * 8;

    float acc[4][4][4];
#pragma unroll
    for (int mt = 0; mt < 4; mt++)
#pragma unroll
        for (int nt = 0; nt < 4; nt++)
#pragma unroll
            for (int u = 0; u < 4; u++) acc[mt][nt][u] = 0.f;

    const int mw = wid & 1, nw = wid >> 1;
    const int m0w = mw * 64, n0w = nw * 32;
    const int am = lane >> 3, ar = lane & 7;

    // staging lambda
    auto stage = [&](int c) {
        int buf = c & 1;
        uint32_t sbase = sb + buf * BUF_B;
#pragma unroll
        for (int i = 0; i < 4; i++) {       // A (gathered, split)
            int g = tid + i * 256;
            int row = g >> 3, seg = g & 7;
            const __nv_bfloat16 *sh, *sl;
            size_t so;
            if (c < 4) { so = (size_t)childs[row] * 256 + c * 64 + seg * 8; sh = g_hsp0; sl = g_hsp1; }
            else       { so = (size_t)(m0 + row) * 256 + (c - 4) * 64 + seg * 8; sh = Hh_in; sl = Hl_in; }
            uint32_t d = sbase + row * 144 + seg * 16;
            CP_ASYNC16(d,           sh + so);
            CP_ASYNC16(d + SPLIT_B, sl + so);
        }
        const __nv_bfloat16* bh = g_Bp0 + (bblk + c) * 8192u;
        const __nv_bfloat16* bl = g_Bp1 + (bblk + c) * 8192u;
#pragma unroll
        for (int i = 0; i < 4; i++) {       // B (linear)
            int g = tid + i * 256;
            int row = g >> 3, seg = g & 7;
            uint32_t d = sbase + 2 * SPLIT_B + row * 144 + seg * 16;
            CP_ASYNC16(d,           bh + row * 64 + seg * 8);
            CP_ASYNC16(d + SPLIT_B, bl + row * 64 + seg * 8);
        }
        CP_COMMIT();
    };

    auto compute = [&](int c) {
        int buf = c & 1;
        uint32_t aH = sb + buf * BUF_B;
        uint32_t aL = aH + SPLIT_B;
        uint32_t bH = aH + 2 * SPLIT_B;
        uint32_t bL = aH + 3 * SPLIT_B;
#pragma unroll
        for (int ks = 0; ks < 4; ks++) {
            int k0 = ks * 16;
            uint32_t ah[4][4], al[4][4], bhf[4][2], blf[4][2];
            // A frags: matrix am: rows +((am&1)?8:0), k +((am>=2)?8:0)
            int arow_off = ((am & 1) ? 8 : 0) + ar;
            int akk = (k0 + ((am >= 2) ? 8 : 0)) * 2;
#pragma unroll
            for (int mt = 0; mt < 4; mt++) {
                uint32_t off = (uint32_t)(m0w + mt * 16 + arow_off) * 144 + akk;
                ldsm4(ah[mt], aH + off);
                ldsm4(al[mt], aL + off);
            }
            // B frags: matrix am: rows +((am>=2)?8:0), k +((am&1)?8:0)
            int brow_off = ((am >= 2) ? 8 : 0) + ar;
            int bkk = (k0 + ((am & 1) ? 8 : 0)) * 2;
#pragma unroll
            for (int np = 0; np < 2; np++) {
                uint32_t off = (uint32_t)(n0w + np * 16 + brow_off) * 144 + bkk;
                uint32_t r[4];
                ldsm4(r, bH + off);
                bhf[np * 2][0] = r[0]; bhf[np * 2][1] = r[1];
                bhf[np * 2 + 1][0] = r[2]; bhf[np * 2 + 1][1] = r[3];
                ldsm4(r, bL + off);
                blf[np * 2][0] = r[0]; blf[np * 2][1] = r[1];
                blf[np * 2 + 1][0] = r[2]; blf[np * 2 + 1][1] = r[3];
            }
#pragma unroll
            for (int mt = 0; mt < 4; mt++)
#pragma unroll
                for (int nt = 0; nt < 4; nt++) {
                    mma_bf16(acc[mt][nt], ah[mt], bhf[nt]);
                    mma_bf16(acc[mt][nt], ah[mt], blf[nt]);
                    mma_bf16(acc[mt][nt], al[mt], bhf[nt]);
                }
        }
    };

    stage(0);
    for (int c = 1; c < 8; c++) {
        stage(c);
        CP_WAIT(1);
        __syncthreads();
        compute(c - 1);
        __syncthreads();
    }
    CP_WAIT(0);
    __syncthreads();
    compute(7);
    __syncthreads();

    // epilogue: accums -> smem, then pointwise LSTM
    float* zs = (float*)smem;    // [128][132]
#pragma unroll
    for (int mt = 0; mt < 4; mt++)
#pragma unroll
        for (int nt = 0; nt < 4; nt++) {
            int row = m0w + mt * 16 + (lane >> 2);
            int col = n0w + nt * 8 + (lane & 3) * 2;
            zs[row * 132 + col]           = acc[mt][nt][0];
            zs[row * 132 + col + 1]       = acc[mt][nt][1];
            zs[(row + 8) * 132 + col]     = acc[mt][nt][2];
            zs[(row + 8) * 132 + col + 1] = acc[mt][nt][3];
        }
    __syncthreads();

    const int dsel = gd & 1;
    const bool isG0 = gd < 2;
    const int par = (t + 1) & 1;
#pragma unroll
    for (int i = 0; i < 16; i++) {
        int e = tid + i * 256;
        int row = e >> 5, d = e & 31;
        int s = m0 + row;
        if (s < Mact) {
            int jb = ntile * 32 + d;
            float zi = zs[row * 132 + 4 * d + 0] + lb[gd * 1024 + jb];
            float zf = zs[row * 132 + 4 * d + 1] + lb[gd * 1024 + 256 + jb];
            float zu = zs[row * 132 + 4 * d + 2] + lb[gd * 1024 + 512 + jb];
            float zo = zs[row * 132 + 4 * d + 3] + lb[gd * 1024 + 768 + jb];
            size_t off = (size_t)s * DIMM + jb;
            float cnew = sigm(zf) * g_C[gd][off] + sigm(zi) * tanhf(zu);
            float hnew = sigm(zo) * tanhf(cnew);
            g_C[gd][off] = cnew;
            bsplit(hnew, g_Hh[par][gd][off], g_Hl[par][gd][off]);
            if (isG0) g_Yseq[dsel][((size_t)s * KK + t) * DIMM + jb] = hnew;
        }
    }
}

// ---------------- final combine ----------------
__global__ __launch_bounds__(256) void final_kernel(
    const float* __restrict__ c_tensor, const int* __restrict__ indice,
    const float* __restrict__ fc_w, float* __restrict__ out) {
    int s = blockIdx.x;
    int j = threadIdx.x;
    int orig = g_sorted_orig[s];
    int len  = g_sorted_len[s];
    int par  = len & 1;

    __shared__ float ysm[16][512];
    __shared__ float fcs[8][256];

    for (int idx = j; idx < 16 * 512; idx += 256) {
        int t = idx >> 9;
        int m = idx & 511;
        float v = 0.f;
        if (t < len) {
            v = (m < 256) ? g_Yseq[0][(s * KK + t) * DIMM + m]
                          : g_Yseq[1][(s * KK + t) * DIMM + (m - 256)];
        }
        ysm[t][m] = v;
    }
    __syncthreads();

    float acc[16];
#pragma unroll
    for (int t = 0; t < 16; t++) acc[t] = 0.f;
    for (int mc = 0; mc < 64; mc++) {
        int m0 = mc * 8;
#pragma unroll
        for (int it = 0; it < 8; it++) fcs[it][j] = fc_w[(m0 + it) * 256 + j];
        __syncthreads();
#pragma unroll
        for (int mm = 0; mm < 8; mm++) {
            float b = fcs[mm][j];
#pragma unroll
            for (int t = 0; t < 16; t++) acc[t] = fmaf(ysm[t][m0 + mm], b, acc[t]);
        }
        __syncthreads();
    }

    float Wf = g_Wx[orig * 1024 + j];
    float bf = 0.f;
#pragma unroll
    for (int t = 0; t < 16; t++) {
        if (t < len) {
            int ci = indice[orig * KK + t];
            bf += sigm(Wf + acc[t]) * c_tensor[(size_t)ci * DIMM + j];
        }
    }

    float dots[3];
#pragma unroll
    for (int g = 1; g <= 3; g++) {
        __syncthreads();
        for (int idx = j; idx < 512; idx += 256) {
            int dsel = idx >> 8; int m = idx & 255;
            size_t off = (size_t)s * DIMM + m;
            ysm[0][idx] = __bfloat162float(g_Hh[par][g * 2 + dsel][off])
                        + __bfloat162float(g_Hl[par][g * 2 + dsel][off]);
        }
        __syncthreads();
        float dot = 0.f;
        for (int m = 0; m < 512; m++)
            dot = fmaf(ysm[0][m], fc_w[(g * 512 + m) * 256 + j], dot);
        dots[g - 1] = dot;
    }

    float Wi = g_Wx[orig * 1024 + 256 + j];
    float Wu = g_Wx[orig * 1024 + 512 + j];
    float Wo = g_Wx[orig * 1024 + 768 + j];
    float bi = sigm(dots[0] + Wi);
    float bu = tanhf(dots[1] + Wu);
    float bo = sigm(dots[2] + Wo);
    float nc = bi * bu + bf;
    float nh = bo * tanhf(nc);
    out[(size_t)orig * DIMM + j] = nh;
    out[(size_t)NN * DIMM + (size_t)orig * DIMM + j] = nc;
}

// ---------------- launch ----------------
extern "C" void kernel_launch(void* const* d_in, const int* in_sizes, int n_in,
                              void* d_out, int out_size) {
    const float* x        = (const float*)d_in[0];
    const float* h_tensor = (const float*)d_in[1];
    const float* c_tensor = (const float*)d_in[2];
    const int*   indice   = (const int*)d_in[3];
    const float* W_w      = (const float*)d_in[4];
    const float* W_b      = (const float*)d_in[5];
    const float* lk       = (const float*)d_in[6];
    const float* lr       = (const float*)d_in[7];
    const float* lb       = (const float*)d_in[8];
    const float* ih       = (const float*)d_in[9];
    const float* ic       = (const float*)d_in[10];
    const float* fc       = (const float*)d_in[11];
    float* out = (float*)d_out;

    cudaFuncSetAttribute(step_mma_kernel, cudaFuncAttributeMaxDynamicSharedMemorySize,
                         SMEM_STEP);

    zero_hist_kernel<<<1, 32>>>();
    len_hist_kernel<<<NN / 256, 256>>>(indice);
    prefix_kernel<<<1, 1>>>();
    scatter_kernel<<<NN / 256, 256>>>(indice);
    prep_kernel<<<(GD * NN * DIMM) / 256, 256>>>(ih, ic, lk, lr, h_tensor);
    for (int t = 0; t < 16; t++)
        step_mma_kernel<<<dim3(32, 8, 8), 256, SMEM_STEP>>>(t, indice, lb);
    wx_gemm_kernel<<<dim3(64, 16), 256>>>(x, W_w, W_b);
    final_kernel<<<NN, 256>>>(c_tensor, indice, fc, out);
}

// round 5
// speedup vs baseline: 1.6307x; 1.0262x over previous
#include <cuda_runtime.h>
#include <cuda_bf16.h>
#include <math.h>
#include <cstdint>

#define NN   4096
#define KK   16
#define DIMM 256
#define RR   8192
#define GD   8

// ---- device scratch (static, no allocation) ----
__device__ int   g_hist[17];
__device__ int   g_off[17];
__device__ int   g_cnt[16];
__device__ int   g_sorted_orig[NN];
__device__ int   g_sorted_len[NN];
__device__ float g_Wx[NN * 1024];
__device__ float g_C[GD][NN * DIMM];        // c state fp32
__device__ float g_Yseq[2][NN * KK * DIMM]; // gate-0 (f) fwd/bwd sequence outputs
// split bf16 h/H state + weights
__device__ __nv_bfloat16 g_hsp0[RR * DIMM];          // h_tensor hi
__device__ __nv_bfloat16 g_hsp1[RR * DIMM];          // h_tensor lo
__device__ __nv_bfloat16 g_Hh[2][GD][NN * DIMM];     // H state hi (double buffered)
__device__ __nv_bfloat16 g_Hl[2][GD][NN * DIMM];     // H state lo
// packed weights: [gd][ntile4][chunk8] blocks of 256 n-rows x 64 k halves (K-major BT)
__device__ __nv_bfloat16 g_Bp0[8u * 4u * 8u * 16384u]; // hi
__device__ __nv_bfloat16 g_Bp1[8u * 4u * 8u * 16384u]; // lo

__device__ __forceinline__ float sigm(float x) { return 1.f / (1.f + expf(-x)); }

__device__ __forceinline__ void bsplit(float v, __nv_bfloat16& h, __nv_bfloat16& l) {
    h = __float2bfloat16(v);
    l = __float2bfloat16(v - __bfloat162float(h));
}

// ---- PTX helpers (non-'a' features only: cp.async, ldmatrix, mma.sync) ----
__device__ __forceinline__ uint32_t smem_u32(const void* p) {
    uint32_t a;
    asm("{ .reg .u64 t; cvta.to.shared.u64 t, %1; cvt.u32.u64 %0, t; }" : "=r"(a) : "l"(p));
    return a;
}
#define CP_ASYNC16(dst, src) \
    asm volatile("cp.async.cg.shared.global [%0], [%1], 16;" :: "r"(dst), "l"(src))
#define CP_COMMIT() asm volatile("cp.async.commit_group;" ::: "memory")
#define CP_WAIT(n)  asm volatile("cp.async.wait_group %0;" :: "n"(n) : "memory")

__device__ __forceinline__ void ldsm4(uint32_t* r, uint32_t addr) {
    asm volatile("ldmatrix.sync.aligned.m8n8.x4.shared.b16 {%0,%1,%2,%3}, [%4];"
                 : "=r"(r[0]), "=r"(r[1]), "=r"(r[2]), "=r"(r[3]) : "r"(addr));
}
__device__ __forceinline__ void mma_bf16(float* c, const uint32_t* a, const uint32_t* b) {
    asm volatile("mma.sync.aligned.m16n8k16.row.col.f32.bf16.bf16.f32 "
                 "{%0,%1,%2,%3}, {%4,%5,%6,%7}, {%8,%9}, {%0,%1,%2,%3};"
                 : "+f"(c[0]), "+f"(c[1]), "+f"(c[2]), "+f"(c[3])
                 : "r"(a[0]), "r"(a[1]), "r"(a[2]), "r"(a[3]), "r"(b[0]), "r"(b[1]));
}

// ---------------- sorting by length (desc) ----------------
__global__ void zero_hist_kernel() { if (threadIdx.x < 17) g_hist[threadIdx.x] = 0; }

__global__ void len_hist_kernel(const int* __restrict__ indice) {
    int n = blockIdx.x * blockDim.x + threadIdx.x;
    if (n >= NN) return;
    int len = 0;
#pragma unroll
    for (int k = 0; k < KK; k++) len += (indice[n * KK + k] != -1);
    atomicAdd(&g_hist[len], 1);
}

__global__ void prefix_kernel() {
    if (threadIdx.x != 0 || blockIdx.x != 0) return;
    int run = 0;
    for (int l = 16; l >= 1; l--) { g_off[l] = run; run += g_hist[l]; }
    for (int t = 0; t < 16; t++) g_cnt[t] = g_off[t + 1] + g_hist[t + 1];
}

__global__ void scatter_kernel(const int* __restrict__ indice) {
    int n = blockIdx.x * blockDim.x + threadIdx.x;
    if (n >= NN) return;
    int len = 0;
#pragma unroll
    for (int k = 0; k < KK; k++) len += (indice[n * KK + k] != -1);
    int pos = atomicAdd(&g_off[len], 1);
    g_sorted_orig[pos] = n;
    g_sorted_len[pos]  = len;
}

// ------- prep: split h_tensor, pack/split weights, init states -------
__global__ void prep_kernel(const float* __restrict__ ih, const float* __restrict__ ic,
                            const float* __restrict__ lk, const float* __restrict__ lr,
                            const float* __restrict__ h_tensor) {
    int idx = blockIdx.x * blockDim.x + threadIdx.x;
    if (idx < RR * DIMM) {           // h_tensor split
        bsplit(h_tensor[idx], g_hsp0[idx], g_hsp1[idx]);
    }
    if (idx < 8 * 512 * 1024) {      // weight pack: gate-interleaved, K-major BT blocks
        int gd = idx >> 19;
        int rem = idx & ((1 << 19) - 1);
        int kg = rem >> 10;          // 0..511
        int pc = rem & 1023;         // packed col: 4*j + q (q: 0=i,1=f,2=u,3=o)
        int oc = (pc & 3) * 256 + (pc >> 2);
        float w = (kg < 256) ? lk[((size_t)gd * 256 + kg) * 1024 + oc]
                             : lr[((size_t)gd * 256 + (kg - 256)) * 1024 + oc];
        int ntile = pc >> 8;         // 4 tiles of 256 packed cols
        int n     = pc & 255;
        int chunk = kg >> 6;
        int k     = kg & 63;
        size_t dst = ((size_t)(gd * 4 + ntile) * 8 + chunk) * 16384u + (size_t)n * 64 + k;
        bsplit(w, g_Bp0[dst], g_Bp1[dst]);
    }
    if (idx < GD * NN * DIMM) {      // init H (split) + C
        int j  = idx & (DIMM - 1);
        int gd = idx / (NN * DIMM);
        int r  = idx % (NN * DIMM);
        bsplit(ih[gd * DIMM + j], g_Hh[0][gd][r], g_Hl[0][gd][r]);
        g_C[gd][r] = ic[gd * DIMM + j];
    }
}

// ---------------- W_x = x @ W_w + W_b ----------------
__global__ __launch_bounds__(256) void wx_gemm_kernel(
    const float* __restrict__ A, const float* __restrict__ B, const float* __restrict__ bias) {
    int m0 = blockIdx.x * 64, n0 = blockIdx.y * 64;
    int tid = threadIdx.x, tx = tid & 15, ty = tid >> 4;
    __shared__ __align__(16) float As[32][68];
    __shared__ __align__(16) float Bs[32][64];
    float acc[4][4];
#pragma unroll
    for (int u = 0; u < 4; u++) {
        float b = bias[n0 + tx * 4 + u];
#pragma unroll
        for (int i = 0; i < 4; i++) acc[i][u] = b;
    }
    for (int kb = 0; kb < 8; kb++) {
        int k0 = kb * 32;
        {
            int row = tid >> 2; int kp = (tid & 3) * 8;
            float4 v0 = *(const float4*)(A + (m0 + row) * 256 + k0 + kp);
            float4 v1 = *(const float4*)(A + (m0 + row) * 256 + k0 + kp + 4);
            As[kp + 0][row] = v0.x; As[kp + 1][row] = v0.y; As[kp + 2][row] = v0.z; As[kp + 3][row] = v0.w;
            As[kp + 4][row] = v1.x; As[kp + 5][row] = v1.y; As[kp + 6][row] = v1.z; As[kp + 7][row] = v1.w;
        }
#pragma unroll
        for (int jj = 0; jj < 8; jj++) {
            int l = tid + 256 * jj; int k = l >> 6; int c = l & 63;
            Bs[k][c] = B[(k0 + k) * 1024 + n0 + c];
        }
        __syncthreads();
#pragma unroll
        for (int kk = 0; kk < 32; kk++) {
            float4 av = *(const float4*)&As[kk][ty * 4];
            float4 bv = *(const float4*)&Bs[kk][tx * 4];
            float a[4] = {av.x, av.y, av.z, av.w};
            float b[4] = {bv.x, bv.y, bv.z, bv.w};
#pragma unroll
            for (int i = 0; i < 4; i++)
#pragma unroll
                for (int u = 0; u < 4; u++) acc[i][u] = fmaf(a[i], b[u], acc[i][u]);
        }
        __syncthreads();
    }
#pragma unroll
    for (int i = 0; i < 4; i++) {
        float4 v = make_float4(acc[i][0], acc[i][1], acc[i][2], acc[i][3]);
        *(float4*)&g_Wx[(m0 + ty * 4 + i) * 1024 + n0 + tx * 4] = v;
    }
}

// ---------------- HMMA recurrent step: CTA 128x256, warp 64x64 ----------------
#define SPA       18432                    // 128 rows x 144B
#define SPB       36864                    // 256 rows x 144B
#define BUF_B     (2 * SPA + 2 * SPB)      // 110592
#define SM_CHILD  (2 * BUF_B)              // 221184
#define SMEM_STEP (2 * BUF_B + 512)        // 221696

__global__ __launch_bounds__(256, 1) void step_mma_kernel(
    int t, const int* __restrict__ indice, const float* __restrict__ lb) {
    extern __shared__ __align__(1024) char smem[];
    const int gd = blockIdx.z;
    const int ntile = blockIdx.y;            // 0..3 (256 packed cols each)
    const int Mact = g_cnt[t];
    const int m0 = blockIdx.x * 128;
    if (m0 >= Mact) return;
    const int tid = threadIdx.x;
    const int wid = tid >> 5, lane = tid & 31;
    const uint32_t sb = smem_u32(smem);
    int* childs = (int*)(smem + SM_CHILD);

    if (tid < 128) {
        int s = m0 + tid;
        int ci = 0;
        if (s < Mact) {
            int orig = g_sorted_orig[s];
            int len  = g_sorted_len[s];
            int tt = (gd & 1) ? (len - 1 - t) : t;
            ci = indice[orig * KK + tt];
        }
        childs[tid] = ci;
    }
    __syncthreads();

    const __nv_bfloat16* Hh_in = &g_Hh[t & 1][gd][0];
    const __nv_bfloat16* Hl_in = &g_Hl[t & 1][gd][0];
    const size_t bblk = (size_t)(gd * 4 + ntile) * 8;

    float acc[4][8][4];                      // [mt][nf(8 cols each)][quad]
#pragma unroll
    for (int mt = 0; mt < 4; mt++)
#pragma unroll
        for (int nf = 0; nf < 8; nf++)
#pragma unroll
            for (int u = 0; u < 4; u++) acc[mt][nf][u] = 0.f;

    const int mw = wid & 1, nw = wid >> 1;   // 2 x 4 warp grid
    const int m0w = mw * 64, n0w = nw * 64;
    const int am = lane >> 3, ar = lane & 7;

    auto stage = [&](int c) {
        int buf = c & 1;
        uint32_t aH = sb + buf * BUF_B;
        uint32_t aL = aH + SPA;
        uint32_t bH = aH + 2 * SPA;
        uint32_t bL = bH + SPB;
#pragma unroll
        for (int i = 0; i < 4; i++) {       // A (gathered, split): 1024 segs per split
            int g = tid + i * 256;
            int row = g >> 3, seg = g & 7;
            size_t so;
            const __nv_bfloat16 *sh, *sl;
            if (c < 4) { so = (size_t)childs[row] * 256 + c * 64 + seg * 8; sh = g_hsp0; sl = g_hsp1; }
            else       { so = (size_t)(m0 + row) * 256 + (c - 4) * 64 + seg * 8; sh = Hh_in; sl = Hl_in; }
            uint32_t d = row * 144 + seg * 16;
            CP_ASYNC16(aH + d, sh + so);
            CP_ASYNC16(aL + d, sl + so);
        }
        const __nv_bfloat16* bh = g_Bp0 + (bblk + c) * 16384u;
        const __nv_bfloat16* bl = g_Bp1 + (bblk + c) * 16384u;
#pragma unroll
        for (int i = 0; i < 8; i++) {       // B: 2048 segs per split
            int g = tid + i * 256;
            int row = g >> 3, seg = g & 7;
            uint32_t d = row * 144 + seg * 16;
            CP_ASYNC16(bH + d, bh + row * 64 + seg * 8);
            CP_ASYNC16(bL + d, bl + row * 64 + seg * 8);
        }
        CP_COMMIT();
    };

    auto compute = [&](int c) {
        int buf = c & 1;
        uint32_t aH = sb + buf * BUF_B;
        uint32_t aL = aH + SPA;
        uint32_t bH = aH + 2 * SPA;
        uint32_t bL = bH + SPB;
#pragma unroll
        for (int ks = 0; ks < 4; ks++) {
            int k0 = ks * 16;
            uint32_t ahi[4][4], alo[4][4], bhf[8][2], blf[8][2];
            int arow_off = ((am & 1) ? 8 : 0) + ar;
            int akk = (k0 + ((am >= 2) ? 8 : 0)) * 2;
#pragma unroll
            for (int mt = 0; mt < 4; mt++) {
                uint32_t off = (uint32_t)(m0w + mt * 16 + arow_off) * 144 + akk;
                ldsm4(ahi[mt], aH + off);
                ldsm4(alo[mt], aL + off);
            }
            int brow_off = ((am >= 2) ? 8 : 0) + ar;
            int bkk = (k0 + ((am & 1) ? 8 : 0)) * 2;
#pragma unroll
            for (int np = 0; np < 4; np++) {
                uint32_t off = (uint32_t)(n0w + np * 16 + brow_off) * 144 + bkk;
                uint32_t r[4];
                ldsm4(r, bH + off);
                bhf[np * 2][0] = r[0]; bhf[np * 2][1] = r[1];
                bhf[np * 2 + 1][0] = r[2]; bhf[np * 2 + 1][1] = r[3];
                ldsm4(r, bL + off);
                blf[np * 2][0] = r[0]; blf[np * 2][1] = r[1];
                blf[np * 2 + 1][0] = r[2]; blf[np * 2 + 1][1] = r[3];
            }
#pragma unroll
            for (int mt = 0; mt < 4; mt++)
#pragma unroll
                for (int nf = 0; nf < 8; nf++) {
                    mma_bf16(acc[mt][nf], ahi[mt], bhf[nf]);
                    mma_bf16(acc[mt][nf], ahi[mt], blf[nf]);
                    mma_bf16(acc[mt][nf], alo[mt], bhf[nf]);
                }
        }
    };

    stage(0);
    for (int c = 1; c < 8; c++) {
        stage(c);
        CP_WAIT(1);
        __syncthreads();
        compute(c - 1);
        __syncthreads();
    }
    CP_WAIT(0);
    __syncthreads();
    compute(7);
    __syncthreads();

    // epilogue: accums -> smem (stride 264), then pointwise LSTM
    float* zs = (float*)smem;    // [128][264]
#pragma unroll
    for (int mt = 0; mt < 4; mt++)
#pragma unroll
        for (int nf = 0; nf < 8; nf++) {
            int row = m0w + mt * 16 + (lane >> 2);
            int col = n0w + nf * 8 + (lane & 3) * 2;
            zs[row * 264 + col]           = acc[mt][nf][0];
            zs[row * 264 + col + 1]       = acc[mt][nf][1];
            zs[(row + 8) * 264 + col]     = acc[mt][nf][2];
            zs[(row + 8) * 264 + col + 1] = acc[mt][nf][3];
        }
    __syncthreads();

    const int dsel = gd & 1;
    const bool isG0 = gd < 2;
    const int par = (t + 1) & 1;
#pragma unroll
    for (int i = 0; i < 32; i++) {
        int e = tid + i * 256;              // 128 rows x 64 dims
        int row = e >> 6, d = e & 63;
        int s = m0 + row;
        if (s < Mact) {
            int jb = ntile * 64 + d;
            float zi = zs[row * 264 + 4 * d + 0] + lb[gd * 1024 + jb];
            float zf = zs[row * 264 + 4 * d + 1] + lb[gd * 1024 + 256 + jb];
            float zu = zs[row * 264 + 4 * d + 2] + lb[gd * 1024 + 512 + jb];
            float zo = zs[row * 264 + 4 * d + 3] + lb[gd * 1024 + 768 + jb];
            size_t off = (size_t)s * DIMM + jb;
            float cnew = sigm(zf) * g_C[gd][off] + sigm(zi) * tanhf(zu);
            float hnew = sigm(zo) * tanhf(cnew);
            g_C[gd][off] = cnew;
            bsplit(hnew, g_Hh[par][gd][off], g_Hl[par][gd][off]);
            if (isG0) g_Yseq[dsel][((size_t)s * KK + t) * DIMM + jb] = hnew;
        }
    }
}

// ---------------- final combine ----------------
__global__ __launch_bounds__(256) void final_kernel(
    const float* __restrict__ c_tensor, const int* __restrict__ indice,
    const float* __restrict__ fc_w, float* __restrict__ out) {
    int s = blockIdx.x;
    int j = threadIdx.x;
    int orig = g_sorted_orig[s];
    int len  = g_sorted_len[s];
    int par  = len & 1;

    __shared__ float ysm[16][512];
    __shared__ float fcs[8][256];

    for (int idx = j; idx < 16 * 512; idx += 256) {
        int t = idx >> 9;
        int m = idx & 511;
        float v = 0.f;
        if (t < len) {
            v = (m < 256) ? g_Yseq[0][(s * KK + t) * DIMM + m]
                          : g_Yseq[1][(s * KK + t) * DIMM + (m - 256)];
        }
        ysm[t][m] = v;
    }
    __syncthreads();

    float acc[16];
#pragma unroll
    for (int t = 0; t < 16; t++) acc[t] = 0.f;
    for (int mc = 0; mc < 64; mc++) {
        int m0 = mc * 8;
#pragma unroll
        for (int it = 0; it < 8; it++) fcs[it][j] = fc_w[(m0 + it) * 256 + j];
        __syncthreads();
#pragma unroll
        for (int mm = 0; mm < 8; mm++) {
            float b = fcs[mm][j];
#pragma unroll
            for (int t = 0; t < 16; t++) acc[t] = fmaf(ysm[t][m0 + mm], b, acc[t]);
        }
        __syncthreads();
    }

    float Wf = g_Wx[orig * 1024 + j];
    float bf = 0.f;
#pragma unroll
    for (int t = 0; t < 16; t++) {
        if (t < len) {
            int ci = indice[orig * KK + t];
            bf += sigm(Wf + acc[t]) * c_tensor[(size_t)ci * DIMM + j];
        }
    }

    float dots[3];
#pragma unroll
    for (int g = 1; g <= 3; g++) {
        __syncthreads();
        for (int idx = j; idx < 512; idx += 256) {
            int dsel = idx >> 8; int m = idx & 255;
            size_t off = (size_t)s * DIMM + m;
            ysm[0][idx] = __bfloat162float(g_Hh[par][g * 2 + dsel][off])
                        + __bfloat162float(g_Hl[par][g * 2 + dsel][off]);
        }
        __syncthreads();
        float dot = 0.f;
        for (int m = 0; m < 512; m++)
            dot = fmaf(ysm[0][m], fc_w[(g * 512 + m) * 256 + j], dot);
        dots[g - 1] = dot;
    }

    float Wi = g_Wx[orig * 1024 + 256 + j];
    float Wu = g_Wx[orig * 1024 + 512 + j];
    float Wo = g_Wx[orig * 1024 + 768 + j];
    float bi = sigm(dots[0] + Wi);
    float bu = tanhf(dots[1] + Wu);
    float bo = sigm(dots[2] + Wo);
    float nc = bi * bu + bf;
    float nh = bo * tanhf(nc);
    out[(size_t)orig * DIMM + j] = nh;
    out[(size_t)NN * DIMM + (size_t)orig * DIMM + j] = nc;
}

// ---------------- launch ----------------
extern "C" void kernel_launch(void* const* d_in, const int* in_sizes, int n_in,
                              void* d_out, int out_size) {
    const float* x        = (const float*)d_in[0];
    const float* h_tensor = (const float*)d_in[1];
    const float* c_tensor = (const float*)d_in[2];
    const int*   indice   = (const int*)d_in[3];
    const float* W_w      = (const float*)d_in[4];
    const float* W_b      = (const float*)d_in[5];
    const float* lk       = (const float*)d_in[6];
    const float* lr       = (const float*)d_in[7];
    const float* lb       = (const float*)d_in[8];
    const float* ih       = (const float*)d_in[9];
    const float* ic       = (const float*)d_in[10];
    const float* fc       = (const float*)d_in[11];
    float* out = (float*)d_out;

    cudaFuncSetAttribute(step_mma_kernel, cudaFuncAttributeMaxDynamicSharedMemorySize,
                         SMEM_STEP);

    zero_hist_kernel<<<1, 32>>>();
    len_hist_kernel<<<NN / 256, 256>>>(indice);
    prefix_kernel<<<1, 1>>>();
    scatter_kernel<<<NN / 256, 256>>>(indice);
    prep_kernel<<<(GD * NN * DIMM) / 256, 256>>>(ih, ic, lk, lr, h_tensor);
    for (int t = 0; t < 16; t++)
        step_mma_kernel<<<dim3(32, 4, 8), 256, SMEM_STEP>>>(t, indice, lb);
    wx_gemm_kernel<<<dim3(64, 16), 256>>>(x, W_w, W_b);
    final_kernel<<<NN, 256>>>(c_tensor, indice, fc, out);
}

// round 6
// speedup vs baseline: 1.8451x; 1.1314x over previous
#include <cuda_runtime.h>
#include <cuda_bf16.h>
#include <math.h>
#include <cstdint>

#define NN   4096
#define KK   16
#define DIMM 256
#define RR   8192
#define GD   8

// ---- device scratch (static, no allocation) ----
__device__ int   g_hist[17];
__device__ int   g_off[17];
__device__ int   g_cnt[16];
__device__ int   g_sorted_orig[NN];
__device__ int   g_sorted_len[NN];
__device__ float g_Wx[NN * 1024];
__device__ float g_C[GD][NN * DIMM];        // c state fp32
__device__ float g_Yseq[2][NN * KK * DIMM]; // gate-0 (f) fwd/bwd sequence outputs
// split bf16 h/H state + weights
__device__ __nv_bfloat16 g_hsp0[RR * DIMM];          // h_tensor hi
__device__ __nv_bfloat16 g_hsp1[RR * DIMM];          // h_tensor lo
__device__ __nv_bfloat16 g_Hh[2][GD][NN * DIMM];     // H state hi (double buffered)
__device__ __nv_bfloat16 g_Hl[2][GD][NN * DIMM];     // H state lo
// packed weights: [gd][ntile4][chunk8] blocks of 256 n-rows x 64 k halves (K-major BT)
__device__ __nv_bfloat16 g_Bp0[8u * 4u * 8u * 16384u]; // hi
__device__ __nv_bfloat16 g_Bp1[8u * 4u * 8u * 16384u]; // lo

__device__ __forceinline__ float sigm(float x) { return 1.f / (1.f + expf(-x)); }

__device__ __forceinline__ void bsplit(float v, __nv_bfloat16& h, __nv_bfloat16& l) {
    h = __float2bfloat16(v);
    l = __float2bfloat16(v - __bfloat162float(h));
}

// ---- PTX helpers (non-'a' features only: cp.async, ldmatrix, mma.sync) ----
__device__ __forceinline__ uint32_t smem_u32(const void* p) {
    uint32_t a;
    asm("{ .reg .u64 t; cvta.to.shared.u64 t, %1; cvt.u32.u64 %0, t; }" : "=r"(a) : "l"(p));
    return a;
}
#define CP_ASYNC16(dst, src) \
    asm volatile("cp.async.cg.shared.global [%0], [%1], 16;" :: "r"(dst), "l"(src))
#define CP_COMMIT() asm volatile("cp.async.commit_group;" ::: "memory")
#define CP_WAIT(n)  asm volatile("cp.async.wait_group %0;" :: "n"(n) : "memory")

__device__ __forceinline__ void ldsm4(uint32_t* r, uint32_t addr) {
    asm volatile("ldmatrix.sync.aligned.m8n8.x4.shared.b16 {%0,%1,%2,%3}, [%4];"
                 : "=r"(r[0]), "=r"(r[1]), "=r"(r[2]), "=r"(r[3]) : "r"(addr));
}
__device__ __forceinline__ void ldsm2(uint32_t* r, uint32_t addr) {
    asm volatile("ldmatrix.sync.aligned.m8n8.x2.shared.b16 {%0,%1}, [%2];"
                 : "=r"(r[0]), "=r"(r[1]) : "r"(addr));
}
__device__ __forceinline__ void mma_bf16(float* c, const uint32_t* a, const uint32_t* b) {
    asm volatile("mma.sync.aligned.m16n8k16.row.col.f32.bf16.bf16.f32 "
                 "{%0,%1,%2,%3}, {%4,%5,%6,%7}, {%8,%9}, {%0,%1,%2,%3};"
                 : "+f"(c[0]), "+f"(c[1]), "+f"(c[2]), "+f"(c[3])
                 : "r"(a[0]), "r"(a[1]), "r"(a[2]), "r"(a[3]), "r"(b[0]), "r"(b[1]));
}

// ---------------- sorting by length (desc) ----------------
__global__ void zero_hist_kernel() { if (threadIdx.x < 17) g_hist[threadIdx.x] = 0; }

__global__ void len_hist_kernel(const int* __restrict__ indice) {
    int n = blockIdx.x * blockDim.x + threadIdx.x;
    if (n >= NN) return;
    int len = 0;
#pragma unroll
    for (int k = 0; k < KK; k++) len += (indice[n * KK + k] != -1);
    atomicAdd(&g_hist[len], 1);
}

__global__ void prefix_kernel() {
    if (threadIdx.x != 0 || blockIdx.x != 0) return;
    int run = 0;
    for (int l = 16; l >= 1; l--) { g_off[l] = run; run += g_hist[l]; }
    for (int t = 0; t < 16; t++) g_cnt[t] = g_off[t + 1] + g_hist[t + 1];
}

__global__ void scatter_kernel(const int* __restrict__ indice) {
    int n = blockIdx.x * blockDim.x + threadIdx.x;
    if (n >= NN) return;
    int len = 0;
#pragma unroll
    for (int k = 0; k < KK; k++) len += (indice[n * KK + k] != -1);
    int pos = atomicAdd(&g_off[len], 1);
    g_sorted_orig[pos] = n;
    g_sorted_len[pos]  = len;
}

// ------- prep: split h_tensor, pack/split weights, init states -------
__global__ void prep_kernel(const float* __restrict__ ih, const float* __restrict__ ic,
                            const float* __restrict__ lk, const float* __restrict__ lr,
                            const float* __restrict__ h_tensor) {
    int idx = blockIdx.x * blockDim.x + threadIdx.x;
    if (idx < RR * DIMM) {           // h_tensor split
        bsplit(h_tensor[idx], g_hsp0[idx], g_hsp1[idx]);
    }
    if (idx < 8 * 512 * 1024) {      // weight pack: gate-interleaved, K-major BT blocks
        int gd = idx >> 19;
        int rem = idx & ((1 << 19) - 1);
        int kg = rem >> 10;          // 0..511
        int pc = rem & 1023;         // packed col: 4*j + q (q: 0=i,1=f,2=u,3=o)
        int oc = (pc & 3) * 256 + (pc >> 2);
        float w = (kg < 256) ? lk[((size_t)gd * 256 + kg) * 1024 + oc]
                             : lr[((size_t)gd * 256 + (kg - 256)) * 1024 + oc];
        int ntile = pc >> 8;         // 4 tiles of 256 packed cols
        int n     = pc & 255;
        int chunk = kg >> 6;
        int k     = kg & 63;
        size_t dst = ((size_t)(gd * 4 + ntile) * 8 + chunk) * 16384u + (size_t)n * 64 + k;
        bsplit(w, g_Bp0[dst], g_Bp1[dst]);
    }
    if (idx < GD * NN * DIMM) {      // init H (split) + C
        int j  = idx & (DIMM - 1);
        int gd = idx / (NN * DIMM);
        int r  = idx % (NN * DIMM);
        bsplit(ih[gd * DIMM + j], g_Hh[0][gd][r], g_Hl[0][gd][r]);
        g_C[gd][r] = ic[gd * DIMM + j];
    }
}

// ---------------- W_x = x @ W_w + W_b ----------------
__global__ __launch_bounds__(256) void wx_gemm_kernel(
    const float* __restrict__ A, const float* __restrict__ B, const float* __restrict__ bias) {
    int m0 = blockIdx.x * 64, n0 = blockIdx.y * 64;
    int tid = threadIdx.x, tx = tid & 15, ty = tid >> 4;
    __shared__ __align__(16) float As[32][68];
    __shared__ __align__(16) float Bs[32][64];
    float acc[4][4];
#pragma unroll
    for (int u = 0; u < 4; u++) {
        float b = bias[n0 + tx * 4 + u];
#pragma unroll
        for (int i = 0; i < 4; i++) acc[i][u] = b;
    }
    for (int kb = 0; kb < 8; kb++) {
        int k0 = kb * 32;
        {
            int row = tid >> 2; int kp = (tid & 3) * 8;
            float4 v0 = *(const float4*)(A + (m0 + row) * 256 + k0 + kp);
            float4 v1 = *(const float4*)(A + (m0 + row) * 256 + k0 + kp + 4);
            As[kp + 0][row] = v0.x; As[kp + 1][row] = v0.y; As[kp + 2][row] = v0.z; As[kp + 3][row] = v0.w;
            As[kp + 4][row] = v1.x; As[kp + 5][row] = v1.y; As[kp + 6][row] = v1.z; As[kp + 7][row] = v1.w;
        }
#pragma unroll
        for (int jj = 0; jj < 8; jj++) {
            int l = tid + 256 * jj; int k = l >> 6; int c = l & 63;
            Bs[k][c] = B[(k0 + k) * 1024 + n0 + c];
        }
        __syncthreads();
#pragma unroll
        for (int kk = 0; kk < 32; kk++) {
            float4 av = *(const float4*)&As[kk][ty * 4];
            float4 bv = *(const float4*)&Bs[kk][tx * 4];
            float a[4] = {av.x, av.y, av.z, av.w};
            float b[4] = {bv.x, bv.y, bv.z, bv.w};
#pragma unroll
            for (int i = 0; i < 4; i++)
#pragma unroll
                for (int u = 0; u < 4; u++) acc[i][u] = fmaf(a[i], b[u], acc[i][u]);
        }
        __syncthreads();
    }
#pragma unroll
    for (int i = 0; i < 4; i++) {
        float4 v = make_float4(acc[i][0], acc[i][1], acc[i][2], acc[i][3]);
        *(float4*)&g_Wx[(m0 + ty * 4 + i) * 1024 + n0 + tx * 4] = v;
    }
}

// ---------------- HMMA recurrent step: CTA 128x256, 16 warps, warp 32x64 ----------------
#define SPA       18432                    // 128 rows x 144B
#define SPB       36864                    // 256 rows x 144B
#define BUF_B     (2 * SPA + 2 * SPB)      // 110592
#define SM_CHILD  (2 * BUF_B)              // 221184
#define SMEM_STEP (2 * BUF_B + 512)        // 221696
#define NT        512

__global__ __launch_bounds__(NT, 1) void step_mma_kernel(
    int t, const int* __restrict__ indice, const float* __restrict__ lb) {
    extern __shared__ __align__(1024) char smem[];
    const int gd = blockIdx.z;
    const int ntile = blockIdx.y;            // 0..3 (256 packed cols each)
    const int Mact = g_cnt[t];
    const int m0 = blockIdx.x * 128;
    if (m0 >= Mact) return;
    const int tid = threadIdx.x;
    const int wid = tid >> 5, lane = tid & 31;
    const uint32_t sb = smem_u32(smem);
    int* childs = (int*)(smem + SM_CHILD);

    if (tid < 128) {
        int s = m0 + tid;
        int ci = 0;
        if (s < Mact) {
            int orig = g_sorted_orig[s];
            int len  = g_sorted_len[s];
            int tt = (gd & 1) ? (len - 1 - t) : t;
            ci = indice[orig * KK + tt];
        }
        childs[tid] = ci;
    }
    __syncthreads();

    const __nv_bfloat16* Hh_in = &g_Hh[t & 1][gd][0];
    const __nv_bfloat16* Hl_in = &g_Hl[t & 1][gd][0];
    const size_t bblk = (size_t)(gd * 4 + ntile) * 8;

    float acc[2][8][4];                      // warp tile 32x64: [mt2][nf8][quad]
#pragma unroll
    for (int mt = 0; mt < 2; mt++)
#pragma unroll
        for (int nf = 0; nf < 8; nf++)
#pragma unroll
            for (int u = 0; u < 4; u++) acc[mt][nf][u] = 0.f;

    const int mw = wid & 3, nw = wid >> 2;   // 4 x 4 warp grid
    const int m0w = mw * 32, n0w = nw * 64;
    const int am = lane >> 3, ar = lane & 7;

    auto stage = [&](int c) {
        int buf = c & 1;
        uint32_t aH = sb + buf * BUF_B;
        uint32_t aL = aH + SPA;
        uint32_t bH = aH + 2 * SPA;
        uint32_t bL = bH + SPB;
#pragma unroll
        for (int i = 0; i < 2; i++) {       // A: 1024 segs per split
            int g = tid + i * NT;
            int row = g >> 3, seg = g & 7;
            size_t so;
            const __nv_bfloat16 *sh, *sl;
            if (c < 4) { so = (size_t)childs[row] * 256 + c * 64 + seg * 8; sh = g_hsp0; sl = g_hsp1; }
            else       { so = (size_t)(m0 + row) * 256 + (c - 4) * 64 + seg * 8; sh = Hh_in; sl = Hl_in; }
            uint32_t d = row * 144 + seg * 16;
            CP_ASYNC16(aH + d, sh + so);
            CP_ASYNC16(aL + d, sl + so);
        }
        const __nv_bfloat16* bh = g_Bp0 + (bblk + c) * 16384u;
        const __nv_bfloat16* bl = g_Bp1 + (bblk + c) * 16384u;
#pragma unroll
        for (int i = 0; i < 4; i++) {       // B: 2048 segs per split
            int g = tid + i * NT;
            int row = g >> 3, seg = g & 7;
            uint32_t d = row * 144 + seg * 16;
            CP_ASYNC16(bH + d, bh + row * 64 + seg * 8);
            CP_ASYNC16(bL + d, bl + row * 64 + seg * 8);
        }
        CP_COMMIT();
    };

    auto compute = [&](int c) {
        int buf = c & 1;
        uint32_t aH = sb + buf * BUF_B;
        uint32_t aL = aH + SPA;
        uint32_t bH = aH + 2 * SPA;
        uint32_t bL = bH + SPB;
#pragma unroll
        for (int ks = 0; ks < 4; ks++) {
            int k0 = ks * 16;
            uint32_t ahi[2][4], alo[2][4];
            int arow_off = ((am & 1) ? 8 : 0) + ar;
            int akk = (k0 + ((am >= 2) ? 8 : 0)) * 2;
#pragma unroll
            for (int mt = 0; mt < 2; mt++) {
                uint32_t off = (uint32_t)(m0w + mt * 16 + arow_off) * 144 + akk;
                ldsm4(ahi[mt], aH + off);
                ldsm4(alo[mt], aL + off);
            }
            int brow_off = ((am >= 2) ? 8 : 0) + ar;
            int bkk = (k0 + ((am & 1) ? 8 : 0)) * 2;
#pragma unroll
            for (int np = 0; np < 4; np++) {
                uint32_t off = (uint32_t)(n0w + np * 16 + brow_off) * 144 + bkk;
                uint32_t rh[4], rl[4];
                ldsm4(rh, bH + off);
                ldsm4(rl, bL + off);
                uint32_t bh0[2] = {rh[0], rh[1]}, bh1[2] = {rh[2], rh[3]};
                uint32_t bl0[2] = {rl[0], rl[1]}, bl1[2] = {rl[2], rl[3]};
#pragma unroll
                for (int mt = 0; mt < 2; mt++) {
                    mma_bf16(acc[mt][np * 2], ahi[mt], bh0);
                    mma_bf16(acc[mt][np * 2 + 1], ahi[mt], bh1);
                    mma_bf16(acc[mt][np * 2], ahi[mt], bl0);
                    mma_bf16(acc[mt][np * 2 + 1], ahi[mt], bl1);
                    mma_bf16(acc[mt][np * 2], alo[mt], bh0);
                    mma_bf16(acc[mt][np * 2 + 1], alo[mt], bh1);
                }
            }
        }
    };

    stage(0);
    for (int c = 1; c < 8; c++) {
        stage(c);
        CP_WAIT(1);
        __syncthreads();
        compute(c - 1);
        __syncthreads();
    }
    CP_WAIT(0);
    __syncthreads();
    compute(7);
    __syncthreads();

    // epilogue: accums -> smem (stride 264), then pointwise LSTM
    float* zs = (float*)smem;    // [128][264]
#pragma unroll
    for (int mt = 0; mt < 2; mt++)
#pragma unroll
        for (int nf = 0; nf < 8; nf++) {
            int row = m0w + mt * 16 + (lane >> 2);
            int col = n0w + nf * 8 + (lane & 3) * 2;
            zs[row * 264 + col]           = acc[mt][nf][0];
            zs[row * 264 + col + 1]       = acc[mt][nf][1];
            zs[(row + 8) * 264 + col]     = acc[mt][nf][2];
            zs[(row + 8) * 264 + col + 1] = acc[mt][nf][3];
        }
    __syncthreads();

    const int dsel = gd & 1;
    const bool isG0 = gd < 2;
    const int par = (t + 1) & 1;
#pragma unroll
    for (int i = 0; i < 16; i++) {
        int e = tid + i * NT;               // 128 rows x 64 dims
        int row = e >> 6, d = e & 63;
        int s = m0 + row;
        if (s < Mact) {
            int jb = ntile * 64 + d;
            float zi = zs[row * 264 + 4 * d + 0] + lb[gd * 1024 + jb];
            float zf = zs[row * 264 + 4 * d + 1] + lb[gd * 1024 + 256 + jb];
            float zu = zs[row * 264 + 4 * d + 2] + lb[gd * 1024 + 512 + jb];
            float zo = zs[row * 264 + 4 * d + 3] + lb[gd * 1024 + 768 + jb];
            size_t off = (size_t)s * DIMM + jb;
            float cnew = sigm(zf) * g_C[gd][off] + sigm(zi) * tanhf(zu);
            float hnew = sigm(zo) * tanhf(cnew);
            g_C[gd][off] = cnew;
            bsplit(hnew, g_Hh[par][gd][off], g_Hl[par][gd][off]);
            if (isG0) g_Yseq[dsel][((size_t)s * KK + t) * DIMM + jb] = hnew;
        }
    }
}

// ---------------- final combine ----------------
__global__ __launch_bounds__(256) void final_kernel(
    const float* __restrict__ c_tensor, const int* __restrict__ indice,
    const float* __restrict__ fc_w, float* __restrict__ out) {
    int s = blockIdx.x;
    int j = threadIdx.x;
    int orig = g_sorted_orig[s];
    int len  = g_sorted_len[s];
    int par  = len & 1;

    __shared__ float ysm[16][512];
    __shared__ float fcs[8][256];

    for (int idx = j; idx < 16 * 512; idx += 256) {
        int t = idx >> 9;
        int m = idx & 511;
        float v = 0.f;
        if (t < len) {
            v = (m < 256) ? g_Yseq[0][(s * KK + t) * DIMM + m]
                          : g_Yseq[1][(s * KK + t) * DIMM + (m - 256)];
        }
        ysm[t][m] = v;
    }
    __syncthreads();

    float acc[16];
#pragma unroll
    for (int t = 0; t < 16; t++) acc[t] = 0.f;
    for (int mc = 0; mc < 64; mc++) {
        int m0 = mc * 8;
#pragma unroll
        for (int it = 0; it < 8; it++) fcs[it][j] = fc_w[(m0 + it) * 256 + j];
        __syncthreads();
#pragma unroll
        for (int mm = 0; mm < 8; mm++) {
            float b = fcs[mm][j];
#pragma unroll
            for (int t = 0; t < 16; t++) acc[t] = fmaf(ysm[t][m0 + mm], b, acc[t]);
        }
        __syncthreads();
    }

    float Wf = g_Wx[orig * 1024 + j];
    float bf = 0.f;
#pragma unroll
    for (int t = 0; t < 16; t++) {
        if (t < len) {
            int ci = indice[orig * KK + t];
            bf += sigm(Wf + acc[t]) * c_tensor[(size_t)ci * DIMM + j];
        }
    }

    float dots[3];
#pragma unroll
    for (int g = 1; g <= 3; g++) {
        __syncthreads();
        for (int idx = j; idx < 512; idx += 256) {
            int dsel = idx >> 8; int m = idx & 255;
            size_t off = (size_t)s * DIMM + m;
            ysm[0][idx] = __bfloat162float(g_Hh[par][g * 2 + dsel][off])
                        + __bfloat162float(g_Hl[par][g * 2 + dsel][off]);
        }
        __syncthreads();
        float dot = 0.f;
        for (int m = 0; m < 512; m++)
            dot = fmaf(ysm[0][m], fc_w[(g * 512 + m) * 256 + j], dot);
        dots[g - 1] = dot;
    }

    float Wi = g_Wx[orig * 1024 + 256 + j];
    float Wu = g_Wx[orig * 1024 + 512 + j];
    float Wo = g_Wx[orig * 1024 + 768 + j];
    float bi = sigm(dots[0] + Wi);
    float bu = tanhf(dots[1] + Wu);
    float bo = sigm(dots[2] + Wo);
    float nc = bi * bu + bf;
    float nh = bo * tanhf(nc);
    out[(size_t)orig * DIMM + j] = nh;
    out[(size_t)NN * DIMM + (size_t)orig * DIMM + j] = nc;
}

// ---------------- launch ----------------
extern "C" void kernel_launch(void* const* d_in, const int* in_sizes, int n_in,
                              void* d_out, int out_size) {
    const float* x        = (const float*)d_in[0];
    const float* h_tensor = (const float*)d_in[1];
    const float* c_tensor = (const float*)d_in[2];
    const int*   indice   = (const int*)d_in[3];
    const float* W_w      = (const float*)d_in[4];
    const float* W_b      = (const float*)d_in[5];
    const float* lk       = (const float*)d_in[6];
    const float* lr       = (const float*)d_in[7];
    const float* lb       = (const float*)d_in[8];
    const float* ih       = (const float*)d_in[9];
    const float* ic       = (const float*)d_in[10];
    const float* fc       = (const float*)d_in[11];
    float* out = (float*)d_out;

    cudaFuncSetAttribute(step_mma_kernel, cudaFuncAttributeMaxDynamicSharedMemorySize,
                         SMEM_STEP);

    zero_hist_kernel<<<1, 32>>>();
    len_hist_kernel<<<NN / 256, 256>>>(indice);
    prefix_kernel<<<1, 1>>>();
    scatter_kernel<<<NN / 256, 256>>>(indice);
    prep_kernel<<<(GD * NN * DIMM) / 256, 256>>>(ih, ic, lk, lr, h_tensor);
    for (int t = 0; t < 16; t++)
        step_mma_kernel<<<dim3(32, 4, 8), NT, SMEM_STEP>>>(t, indice, lb);
    wx_gemm_kernel<<<dim3(64, 16), 256>>>(x, W_w, W_b);
    final_kernel<<<NN, 256>>>(c_tensor, indice, fc, out);
}

// round 7
// speedup vs baseline: 3.1049x; 1.6828x over previous
#include <cuda_runtime.h>
#include <cuda_fp16.h>
#include <math.h>
#include <cstdint>

#define NN   4096
#define KK   16
#define DIMM 256
#define RR   8192
#define GD   8

// ---- device scratch (static, no allocation) ----
__device__ int   g_hist[17];
__device__ int   g_off[17];
__device__ int   g_cnt[16];
__device__ int   g_sorted_orig[NN];
__device__ int   g_sorted_len[NN];
__device__ float g_Wx[NN * 1024];
__device__ float g_C[GD][NN * DIMM];        // c state fp32
__device__ float g_Yseq[2][NN * KK * DIMM]; // gate-0 (f) fwd/bwd sequence outputs
// fp16 h/H state + weights
__device__ __half g_hf16[RR * DIMM];            // h_tensor (rounded)
__device__ __half g_Hf16[2][GD][NN * DIMM];     // H state (double buffered)
// packed weights: [gd][ntile4][chunk8] blocks of 256 n-rows x 64 k halves (K-major BT)
__device__ __half g_Bpf[8u * 4u * 8u * 16384u];

__device__ __forceinline__ float sigm(float x) { return 1.f / (1.f + expf(-x)); }

// ---- PTX helpers (non-'a' features only: cp.async, ldmatrix, mma.sync) ----
__device__ __forceinline__ uint32_t smem_u32(const void* p) {
    uint32_t a;
    asm("{ .reg .u64 t; cvta.to.shared.u64 t, %1; cvt.u32.u64 %0, t; }" : "=r"(a) : "l"(p));
    return a;
}
#define CP_ASYNC16(dst, src) \
    asm volatile("cp.async.cg.shared.global [%0], [%1], 16;" :: "r"(dst), "l"(src))
#define CP_COMMIT() asm volatile("cp.async.commit_group;" ::: "memory")
#define CP_WAIT(n)  asm volatile("cp.async.wait_group %0;" :: "n"(n) : "memory")

__device__ __forceinline__ void ldsm4(uint32_t* r, uint32_t addr) {
    asm volatile("ldmatrix.sync.aligned.m8n8.x4.shared.b16 {%0,%1,%2,%3}, [%4];"
                 : "=r"(r[0]), "=r"(r[1]), "=r"(r[2]), "=r"(r[3]) : "r"(addr));
}
__device__ __forceinline__ void mma_f16(float* c, const uint32_t* a, const uint32_t* b) {
    asm volatile("mma.sync.aligned.m16n8k16.row.col.f32.f16.f16.f32 "
                 "{%0,%1,%2,%3}, {%4,%5,%6,%7}, {%8,%9}, {%0,%1,%2,%3};"
                 : "+f"(c[0]), "+f"(c[1]), "+f"(c[2]), "+f"(c[3])
                 : "r"(a[0]), "r"(a[1]), "r"(a[2]), "r"(a[3]), "r"(b[0]), "r"(b[1]));
}

// ---------------- sorting by length (desc) ----------------
__global__ void zero_hist_kernel() { if (threadIdx.x < 17) g_hist[threadIdx.x] = 0; }

__global__ void len_hist_kernel(const int* __restrict__ indice) {
    int n = blockIdx.x * blockDim.x + threadIdx.x;
    if (n >= NN) return;
    int len = 0;
#pragma unroll
    for (int k = 0; k < KK; k++) len += (indice[n * KK + k] != -1);
    atomicAdd(&g_hist[len], 1);
}

__global__ void prefix_kernel() {
    if (threadIdx.x != 0 || blockIdx.x != 0) return;
    int run = 0;
    for (int l = 16; l >= 1; l--) { g_off[l] = run; run += g_hist[l]; }
    for (int t = 0; t < 16; t++) g_cnt[t] = g_off[t + 1] + g_hist[t + 1];
}

__global__ void scatter_kernel(const int* __restrict__ indice) {
    int n = blockIdx.x * blockDim.x + threadIdx.x;
    if (n >= NN) return;
    int len = 0;
#pragma unroll
    for (int k = 0; k < KK; k++) len += (indice[n * KK + k] != -1);
    int pos = atomicAdd(&g_off[len], 1);
    g_sorted_orig[pos] = n;
    g_sorted_len[pos]  = len;
}

// ------- prep: round h_tensor, pack weights, init states -------
__global__ void prep_kernel(const float* __restrict__ ih, const float* __restrict__ ic,
                            const float* __restrict__ lk, const float* __restrict__ lr,
                            const float* __restrict__ h_tensor) {
    int idx = blockIdx.x * blockDim.x + threadIdx.x;
    if (idx < RR * DIMM) {           // h_tensor round
        g_hf16[idx] = __float2half(h_tensor[idx]);
    }
    if (idx < 8 * 512 * 1024) {      // weight pack: gate-interleaved, K-major BT blocks
        int gd = idx >> 19;
        int rem = idx & ((1 << 19) - 1);
        int kg = rem >> 10;          // 0..511
        int pc = rem & 1023;         // packed col: 4*j + q (q: 0=i,1=f,2=u,3=o)
        int oc = (pc & 3) * 256 + (pc >> 2);
        float w = (kg < 256) ? lk[((size_t)gd * 256 + kg) * 1024 + oc]
                             : lr[((size_t)gd * 256 + (kg - 256)) * 1024 + oc];
        int ntile = pc >> 8;         // 4 tiles of 256 packed cols
        int n     = pc & 255;
        int chunk = kg >> 6;
        int k     = kg & 63;
        size_t dst = ((size_t)(gd * 4 + ntile) * 8 + chunk) * 16384u + (size_t)n * 64 + k;
        g_Bpf[dst] = __float2half(w);
    }
    if (idx < GD * NN * DIMM) {      // init H + C
        int j  = idx & (DIMM - 1);
        int gd = idx / (NN * DIMM);
        int r  = idx % (NN * DIMM);
        g_Hf16[0][gd][r] = __float2half(ih[gd * DIMM + j]);
        g_C[gd][r] = ic[gd * DIMM + j];
    }
}

// ---------------- W_x = x @ W_w + W_b ----------------
__global__ __launch_bounds__(256) void wx_gemm_kernel(
    const float* __restrict__ A, const float* __restrict__ B, const float* __restrict__ bias) {
    int m0 = blockIdx.x * 64, n0 = blockIdx.y * 64;
    int tid = threadIdx.x, tx = tid & 15, ty = tid >> 4;
    __shared__ __align__(16) float As[32][68];
    __shared__ __align__(16) float Bs[32][64];
    float acc[4][4];
#pragma unroll
    for (int u = 0; u < 4; u++) {
        float b = bias[n0 + tx * 4 + u];
#pragma unroll
        for (int i = 0; i < 4; i++) acc[i][u] = b;
    }
    for (int kb = 0; kb < 8; kb++) {
        int k0 = kb * 32;
        {
            int row = tid >> 2; int kp = (tid & 3) * 8;
            float4 v0 = *(const float4*)(A + (m0 + row) * 256 + k0 + kp);
            float4 v1 = *(const float4*)(A + (m0 + row) * 256 + k0 + kp + 4);
            As[kp + 0][row] = v0.x; As[kp + 1][row] = v0.y; As[kp + 2][row] = v0.z; As[kp + 3][row] = v0.w;
            As[kp + 4][row] = v1.x; As[kp + 5][row] = v1.y; As[kp + 6][row] = v1.z; As[kp + 7][row] = v1.w;
        }
#pragma unroll
        for (int jj = 0; jj < 8; jj++) {
            int l = tid + 256 * jj; int k = l >> 6; int c = l & 63;
            Bs[k][c] = B[(k0 + k) * 1024 + n0 + c];
        }
        __syncthreads();
#pragma unroll
        for (int kk = 0; kk < 32; kk++) {
            float4 av = *(const float4*)&As[kk][ty * 4];
            float4 bv = *(const float4*)&Bs[kk][tx * 4];
            float a[4] = {av.x, av.y, av.z, av.w};
            float b[4] = {bv.x, bv.y, bv.z, bv.w};
#pragma unroll
            for (int i = 0; i < 4; i++)
#pragma unroll
                for (int u = 0; u < 4; u++) acc[i][u] = fmaf(a[i], b[u], acc[i][u]);
        }
        __syncthreads();
    }
#pragma unroll
    for (int i = 0; i < 4; i++) {
        float4 v = make_float4(acc[i][0], acc[i][1], acc[i][2], acc[i][3]);
        *(float4*)&g_Wx[(m0 + ty * 4 + i) * 1024 + n0 + tx * 4] = v;
    }
}

// ---- HMMA recurrent step: CTA 128x256, 16 warps, warp 32x64, fp16 1-term, 3-deep pipe ----
#define SPA       18432                    // 128 rows x 144B
#define SPB       36864                    // 256 rows x 144B
#define BUF_B     (SPA + SPB)              // 55296
#define SM_CHILD  (3 * BUF_B)              // 165888
#define SMEM_STEP (3 * BUF_B + 512)        // 166400
#define NT        512

__global__ __launch_bounds__(NT, 1) void step_mma_kernel(
    int t, const int* __restrict__ indice, const float* __restrict__ lb) {
    extern __shared__ __align__(1024) char smem[];
    const int gd = blockIdx.z;
    const int ntile = blockIdx.y;            // 0..3 (256 packed cols each)
    const int Mact = g_cnt[t];
    const int m0 = blockIdx.x * 128;
    if (m0 >= Mact) return;
    const int tid = threadIdx.x;
    const int wid = tid >> 5, lane = tid & 31;
    const uint32_t sb = smem_u32(smem);
    int* childs = (int*)(smem + SM_CHILD);

    if (tid < 128) {
        int s = m0 + tid;
        int ci = 0;
        if (s < Mact) {
            int orig = g_sorted_orig[s];
            int len  = g_sorted_len[s];
            int tt = (gd & 1) ? (len - 1 - t) : t;
            ci = indice[orig * KK + tt];
        }
        childs[tid] = ci;
    }
    __syncthreads();

    const __half* Hin = &g_Hf16[t & 1][gd][0];
    const size_t bblk = (size_t)(gd * 4 + ntile) * 8;

    float acc[2][8][4];                      // warp tile 32x64: [mt2][nf8][quad]
#pragma unroll
    for (int mt = 0; mt < 2; mt++)
#pragma unroll
        for (int nf = 0; nf < 8; nf++)
#pragma unroll
            for (int u = 0; u < 4; u++) acc[mt][nf][u] = 0.f;

    const int mw = wid & 3, nw = wid >> 2;   // 4 x 4 warp grid
    const int m0w = mw * 32, n0w = nw * 64;
    const int am = lane >> 3, ar = lane & 7;

    auto stage = [&](int c) {
        uint32_t base = sb + (c % 3) * BUF_B;
        uint32_t aS = base;
        uint32_t bS = base + SPA;
#pragma unroll
        for (int i = 0; i < 2; i++) {       // A: 1024 segs of 16B
            int g = tid + i * NT;
            int row = g >> 3, seg = g & 7;
            const __half* src;
            if (c < 4) src = g_hf16 + (size_t)childs[row] * 256 + c * 64 + seg * 8;
            else       src = Hin + (size_t)(m0 + row) * 256 + (c - 4) * 64 + seg * 8;
            CP_ASYNC16(aS + row * 144 + seg * 16, src);
        }
        const __half* bw = g_Bpf + (bblk + c) * 16384u;
#pragma unroll
        for (int i = 0; i < 4; i++) {       // B: 2048 segs of 16B
            int g = tid + i * NT;
            int row = g >> 3, seg = g & 7;
            CP_ASYNC16(bS + row * 144 + seg * 16, bw + row * 64 + seg * 8);
        }
        CP_COMMIT();
    };

    auto compute = [&](int c) {
        uint32_t base = sb + (c % 3) * BUF_B;
        uint32_t aS = base;
        uint32_t bS = base + SPA;
#pragma unroll
        for (int ks = 0; ks < 4; ks++) {
            int k0 = ks * 16;
            uint32_t af[2][4];
            int arow_off = ((am & 1) ? 8 : 0) + ar;
            int akk = (k0 + ((am >= 2) ? 8 : 0)) * 2;
#pragma unroll
            for (int mt = 0; mt < 2; mt++) {
                uint32_t off = (uint32_t)(m0w + mt * 16 + arow_off) * 144 + akk;
                ldsm4(af[mt], aS + off);
            }
            int brow_off = ((am >= 2) ? 8 : 0) + ar;
            int bkk = (k0 + ((am & 1) ? 8 : 0)) * 2;
#pragma unroll
            for (int np = 0; np < 4; np++) {
                uint32_t off = (uint32_t)(n0w + np * 16 + brow_off) * 144 + bkk;
                uint32_t rb[4];
                ldsm4(rb, bS + off);
                uint32_t b0[2] = {rb[0], rb[1]}, b1[2] = {rb[2], rb[3]};
#pragma unroll
                for (int mt = 0; mt < 2; mt++) {
                    mma_f16(acc[mt][np * 2], af[mt], b0);
                    mma_f16(acc[mt][np * 2 + 1], af[mt], b1);
                }
            }
        }
    };

    stage(0);
    stage(1);
#pragma unroll
    for (int c = 0; c < 8; c++) {
        if (c == 7) { CP_WAIT(0); } else { CP_WAIT(1); }
        __syncthreads();
        if (c + 2 < 8) stage(c + 2);
        compute(c);
    }
    __syncthreads();

    // epilogue: accums -> smem (stride 264), then pointwise LSTM
    float* zs = (float*)smem;    // [128][264]
#pragma unroll
    for (int mt = 0; mt < 2; mt++)
#pragma unroll
        for (int nf = 0; nf < 8; nf++) {
            int row = m0w + mt * 16 + (lane >> 2);
            int col = n0w + nf * 8 + (lane & 3) * 2;
            zs[row * 264 + col]           = acc[mt][nf][0];
            zs[row * 264 + col + 1]       = acc[mt][nf][1];
            zs[(row + 8) * 264 + col]     = acc[mt][nf][2];
            zs[(row + 8) * 264 + col + 1] = acc[mt][nf][3];
        }
    __syncthreads();

    const int dsel = gd & 1;
    const bool isG0 = gd < 2;
    const int par = (t + 1) & 1;
#pragma unroll
    for (int i = 0; i < 16; i++) {
        int e = tid + i * NT;               // 128 rows x 64 dims
        int row = e >> 6, d = e & 63;
        int s = m0 + row;
        if (s < Mact) {
            int jb = ntile * 64 + d;
            float zi = zs[row * 264 + 4 * d + 0] + lb[gd * 1024 + jb];
            float zf = zs[row * 264 + 4 * d + 1] + lb[gd * 1024 + 256 + jb];
            float zu = zs[row * 264 + 4 * d + 2] + lb[gd * 1024 + 512 + jb];
            float zo = zs[row * 264 + 4 * d + 3] + lb[gd * 1024 + 768 + jb];
            size_t off = (size_t)s * DIMM + jb;
            float cnew = sigm(zf) * g_C[gd][off] + sigm(zi) * tanhf(zu);
            float hnew = sigm(zo) * tanhf(cnew);
            g_C[gd][off] = cnew;
            g_Hf16[par][gd][off] = __float2half(hnew);
            if (isG0) g_Yseq[dsel][((size_t)s * KK + t) * DIMM + jb] = hnew;
        }
    }
}

// ---------------- final combine ----------------
__global__ __launch_bounds__(256) void final_kernel(
    const float* __restrict__ c_tensor, const int* __restrict__ indice,
    const float* __restrict__ fc_w, float* __restrict__ out) {
    int s = blockIdx.x;
    int j = threadIdx.x;
    int orig = g_sorted_orig[s];
    int len  = g_sorted_len[s];
    int par  = len & 1;

    __shared__ float ysm[16][512];
    __shared__ float fcs[8][256];

    for (int idx = j; idx < 16 * 512; idx += 256) {
        int t = idx >> 9;
        int m = idx & 511;
        float v = 0.f;
        if (t < len) {
            v = (m < 256) ? g_Yseq[0][(s * KK + t) * DIMM + m]
                          : g_Yseq[1][(s * KK + t) * DIMM + (m - 256)];
        }
        ysm[t][m] = v;
    }
    __syncthreads();

    float acc[16];
#pragma unroll
    for (int t = 0; t < 16; t++) acc[t] = 0.f;
    for (int mc = 0; mc < 64; mc++) {
        int m0 = mc * 8;
#pragma unroll
        for (int it = 0; it < 8; it++) fcs[it][j] = fc_w[(m0 + it) * 256 + j];
        __syncthreads();
#pragma unroll
        for (int mm = 0; mm < 8; mm++) {
            float b = fcs[mm][j];
#pragma unroll
            for (int t = 0; t < 16; t++) acc[t] = fmaf(ysm[t][m0 + mm], b, acc[t]);
        }
        __syncthreads();
    }

    float Wf = g_Wx[orig * 1024 + j];
    float bf = 0.f;
#pragma unroll
    for (int t = 0; t < 16; t++) {
        if (t < len) {
            int ci = indice[orig * KK + t];
            bf += sigm(Wf + acc[t]) * c_tensor[(size_t)ci * DIMM + j];
        }
    }

    float dots[3];
#pragma unroll
    for (int g = 1; g <= 3; g++) {
        __syncthreads();
        for (int idx = j; idx < 512; idx += 256) {
            int dsel = idx >> 8; int m = idx & 255;
            size_t off = (size_t)s * DIMM + m;
            ysm[0][idx] = __half2float(g_Hf16[par][g * 2 + dsel][off]);
        }
        __syncthreads();
        float dot = 0.f;
        for (int m = 0; m < 512; m++)
            dot = fmaf(ysm[0][m], fc_w[(g * 512 + m) * 256 + j], dot);
        dots[g - 1] = dot;
    }

    float Wi = g_Wx[orig * 1024 + 256 + j];
    float Wu = g_Wx[orig * 1024 + 512 + j];
    float Wo = g_Wx[orig * 1024 + 768 + j];
    float bi = sigm(dots[0] + Wi);
    float bu = tanhf(dots[1] + Wu);
    float bo = sigm(dots[2] + Wo);
    float nc = bi * bu + bf;
    float nh = bo * tanhf(nc);
    out[(size_t)orig * DIMM + j] = nh;
    out[(size_t)NN * DIMM + (size_t)orig * DIMM + j] = nc;
}

// ---------------- launch ----------------
extern "C" void kernel_launch(void* const* d_in, const int* in_sizes, int n_in,
                              void* d_out, int out_size) {
    const float* x        = (const float*)d_in[0];
    const float* h_tensor = (const float*)d_in[1];
    const float* c_tensor = (const float*)d_in[2];
    const int*   indice   = (const int*)d_in[3];
    const float* W_w      = (const float*)d_in[4];
    const float* W_b      = (const float*)d_in[5];
    const float* lk       = (const float*)d_in[6];
    const float* lr       = (const float*)d_in[7];
    const float* lb       = (const float*)d_in[8];
    const float* ih       = (const float*)d_in[9];
    const float* ic       = (const float*)d_in[10];
    const float* fc       = (const float*)d_in[11];
    float* out = (float*)d_out;

    cudaFuncSetAttribute(step_mma_kernel, cudaFuncAttributeMaxDynamicSharedMemorySize,
                         SMEM_STEP);

    zero_hist_kernel<<<1, 32>>>();
    len_hist_kernel<<<NN / 256, 256>>>(indice);
    prefix_kernel<<<1, 1>>>();
    scatter_kernel<<<NN / 256, 256>>>(indice);
    prep_kernel<<<(GD * NN * DIMM) / 256, 256>>>(ih, ic, lk, lr, h_tensor);
    for (int t = 0; t < 16; t++)
        step_mma_kernel<<<dim3(32, 4, 8), NT, SMEM_STEP>>>(t, indice, lb);
    wx_gemm_kernel<<<dim3(64, 16), 256>>>(x, W_w, W_b);
    final_kernel<<<NN, 256>>>(c_tensor, indice, fc, out);
}

// round 8
// speedup vs baseline: 4.6199x; 1.4880x over previous
#include <cuda_runtime.h>
#include <cuda_fp16.h>
#include <math.h>
#include <cstdint>

#define NN   4096
#define KK   16
#define DIMM 256
#define RR   8192
#define GD   8

// ---- device scratch (static, no allocation) ----
__device__ int   g_hist[17];
__device__ int   g_off[17];
__device__ int   g_cnt[16];
__device__ int   g_sorted_orig[NN];
__device__ int   g_sorted_len[NN];
__device__ float g_Wx[NN * 1024];
__device__ float g_C[GD][NN * DIMM];           // c state fp32
__device__ __half g_Yf16[2][NN * KK * DIMM];   // gate-0 fwd/bwd seq outputs (fp16)
__device__ __half g_Hfin[GD][NN * DIMM];       // final h per gd (fp16)
__device__ float g_fseq[NN * KK * DIMM];       // fc0 projection of ycat
__device__ float g_ydot[3 * NN * DIMM];        // fc1..3 projections of y_last
// fp16 h/H state + weights
__device__ __half g_hf16[RR * DIMM];            // h_tensor (rounded)
__device__ __half g_Hf16[2][GD][NN * DIMM];     // H state (double buffered)
// packed weights: [gd][ntile4][chunk8] blocks of 256 n-rows x 64 k halves (K-major BT)
__device__ __half g_Bpf[8u * 4u * 8u * 16384u];
// packed fc weights: [gate4][256 n][512 k] fp16 (BT, K-major)
__device__ __half g_fcp[4u * 256u * 512u];

__device__ __forceinline__ float sigm(float x) { return 1.f / (1.f + expf(-x)); }

// ---- PTX helpers (non-'a' features only: cp.async, ldmatrix, mma.sync) ----
__device__ __forceinline__ uint32_t smem_u32(const void* p) {
    uint32_t a;
    asm("{ .reg .u64 t; cvta.to.shared.u64 t, %1; cvt.u32.u64 %0, t; }" : "=r"(a) : "l"(p));
    return a;
}
#define CP_ASYNC16(dst, src) \
    asm volatile("cp.async.cg.shared.global [%0], [%1], 16;" :: "r"(dst), "l"(src))
#define CP_COMMIT() asm volatile("cp.async.commit_group;" ::: "memory")
#define CP_WAIT(n)  asm volatile("cp.async.wait_group %0;" :: "n"(n) : "memory")

__device__ __forceinline__ void ldsm4(uint32_t* r, uint32_t addr) {
    asm volatile("ldmatrix.sync.aligned.m8n8.x4.shared.b16 {%0,%1,%2,%3}, [%4];"
                 : "=r"(r[0]), "=r"(r[1]), "=r"(r[2]), "=r"(r[3]) : "r"(addr));
}
__device__ __forceinline__ void mma_f16(float* c, const uint32_t* a, const uint32_t* b) {
    asm volatile("mma.sync.aligned.m16n8k16.row.col.f32.f16.f16.f32 "
                 "{%0,%1,%2,%3}, {%4,%5,%6,%7}, {%8,%9}, {%0,%1,%2,%3};"
                 : "+f"(c[0]), "+f"(c[1]), "+f"(c[2]), "+f"(c[3])
                 : "r"(a[0]), "r"(a[1]), "r"(a[2]), "r"(a[3]), "r"(b[0]), "r"(b[1]));
}

// ---------------- sorting by length (desc) ----------------
__global__ void zero_hist_kernel() { if (threadIdx.x < 17) g_hist[threadIdx.x] = 0; }

__global__ void len_hist_kernel(const int* __restrict__ indice) {
    int n = blockIdx.x * blockDim.x + threadIdx.x;
    if (n >= NN) return;
    int len = 0;
#pragma unroll
    for (int k = 0; k < KK; k++) len += (indice[n * KK + k] != -1);
    atomicAdd(&g_hist[len], 1);
}

__global__ void prefix_kernel() {
    if (threadIdx.x != 0 || blockIdx.x != 0) return;
    int run = 0;
    for (int l = 16; l >= 1; l--) { g_off[l] = run; run += g_hist[l]; }
    for (int t = 0; t < 16; t++) g_cnt[t] = g_off[t + 1] + g_hist[t + 1];
}

__global__ void scatter_kernel(const int* __restrict__ indice) {
    int n = blockIdx.x * blockDim.x + threadIdx.x;
    if (n >= NN) return;
    int len = 0;
#pragma unroll
    for (int k = 0; k < KK; k++) len += (indice[n * KK + k] != -1);
    int pos = atomicAdd(&g_off[len], 1);
    g_sorted_orig[pos] = n;
    g_sorted_len[pos]  = len;
}

// ------- prep: round h_tensor, pack weights (lstm + fc), init states -------
__global__ void prep_kernel(const float* __restrict__ ih, const float* __restrict__ ic,
                            const float* __restrict__ lk, const float* __restrict__ lr,
                            const float* __restrict__ h_tensor,
                            const float* __restrict__ fc_w) {
    int idx = blockIdx.x * blockDim.x + threadIdx.x;
    if (idx < RR * DIMM) {           // h_tensor round
        g_hf16[idx] = __float2half(h_tensor[idx]);
    }
    if (idx < 8 * 512 * 1024) {      // lstm weight pack: gate-interleaved, K-major BT blocks
        int gd = idx >> 19;
        int rem = idx & ((1 << 19) - 1);
        int kg = rem >> 10;          // 0..511
        int pc = rem & 1023;         // packed col: 4*j + q (q: 0=i,1=f,2=u,3=o)
        int oc = (pc & 3) * 256 + (pc >> 2);
        float w = (kg < 256) ? lk[((size_t)gd * 256 + kg) * 1024 + oc]
                             : lr[((size_t)gd * 256 + (kg - 256)) * 1024 + oc];
        int ntile = pc >> 8;         // 4 tiles of 256 packed cols
        int n     = pc & 255;
        int chunk = kg >> 6;
        int k     = kg & 63;
        size_t dst = ((size_t)(gd * 4 + ntile) * 8 + chunk) * 16384u + (size_t)n * 64 + k;
        g_Bpf[dst] = __float2half(w);
    }
    if (idx < 4 * 256 * 512) {       // fc weight pack: BT [gate][n][k]
        int g = idx >> 17;
        int rem = idx & ((1 << 17) - 1);
        int n = rem >> 9, k = rem & 511;
        g_fcp[idx] = __float2half(fc_w[((size_t)g * 512 + k) * 256 + n]);
    }
    if (idx < GD * NN * DIMM) {      // init H + C
        int j  = idx & (DIMM - 1);
        int gd = idx / (NN * DIMM);
        int r  = idx % (NN * DIMM);
        g_Hf16[0][gd][r] = __float2half(ih[gd * DIMM + j]);
        g_C[gd][r] = ic[gd * DIMM + j];
    }
}

// ---------------- W_x = x @ W_w + W_b ----------------
__global__ __launch_bounds__(256) void wx_gemm_kernel(
    const float* __restrict__ A, const float* __restrict__ B, const float* __restrict__ bias) {
    int m0 = blockIdx.x * 64, n0 = blockIdx.y * 64;
    int tid = threadIdx.x, tx = tid & 15, ty = tid >> 4;
    __shared__ __align__(16) float As[32][68];
    __shared__ __align__(16) float Bs[32][64];
    float acc[4][4];
#pragma unroll
    for (int u = 0; u < 4; u++) {
        float b = bias[n0 + tx * 4 + u];
#pragma unroll
        for (int i = 0; i < 4; i++) acc[i][u] = b;
    }
    for (int kb = 0; kb < 8; kb++) {
        int k0 = kb * 32;
        {
            int row = tid >> 2; int kp = (tid & 3) * 8;
            float4 v0 = *(const float4*)(A + (m0 + row) * 256 + k0 + kp);
            float4 v1 = *(const float4*)(A + (m0 + row) * 256 + k0 + kp + 4);
            As[kp + 0][row] = v0.x; As[kp + 1][row] = v0.y; As[kp + 2][row] = v0.z; As[kp + 3][row] = v0.w;
            As[kp + 4][row] = v1.x; As[kp + 5][row] = v1.y; As[kp + 6][row] = v1.z; As[kp + 7][row] = v1.w;
        }
#pragma unroll
        for (int jj = 0; jj < 8; jj++) {
            int l = tid + 256 * jj; int k = l >> 6; int c = l & 63;
            Bs[k][c] = B[(k0 + k) * 1024 + n0 + c];
        }
        __syncthreads();
#pragma unroll
        for (int kk = 0; kk < 32; kk++) {
            float4 av = *(const float4*)&As[kk][ty * 4];
            float4 bv = *(const float4*)&Bs[kk][tx * 4];
            float a[4] = {av.x, av.y, av.z, av.w};
            float b[4] = {bv.x, bv.y, bv.z, bv.w};
#pragma unroll
            for (int i = 0; i < 4; i++)
#pragma unroll
                for (int u = 0; u < 4; u++) acc[i][u] = fmaf(a[i], b[u], acc[i][u]);
        }
        __syncthreads();
    }
#pragma unroll
    for (int i = 0; i < 4; i++) {
        float4 v = make_float4(acc[i][0], acc[i][1], acc[i][2], acc[i][3]);
        *(float4*)&g_Wx[(m0 + ty * 4 + i) * 1024 + n0 + tx * 4] = v;
    }
}

// ---- HMMA recurrent step: CTA 128x256, 16 warps, warp 32x64, fp16, 3-deep pipe ----
#define SPA       18432                    // 128 rows x 144B
#define SPB       36864                    // 256 rows x 144B
#define BUF_B     (SPA + SPB)              // 55296
#define SM_CHILD  (3 * BUF_B)              // 165888
#define SMEM_STEP (3 * BUF_B + 512)        // 166400
#define NT        512

__global__ __launch_bounds__(NT, 1) void step_mma_kernel(
    int t, const int* __restrict__ indice, const float* __restrict__ lb) {
    extern __shared__ __align__(1024) char smem[];
    const int gd = blockIdx.z;
    const int ntile = blockIdx.y;            // 0..3 (256 packed cols each)
    const int Mact = g_cnt[t];
    const int m0 = blockIdx.x * 128;
    if (m0 >= Mact) return;
    const int tid = threadIdx.x;
    const int wid = tid >> 5, lane = tid & 31;
    const uint32_t sb = smem_u32(smem);
    int* childs = (int*)(smem + SM_CHILD);

    if (tid < 128) {
        int s = m0 + tid;
        int ci = 0;
        if (s < Mact) {
            int orig = g_sorted_orig[s];
            int len  = g_sorted_len[s];
            int tt = (gd & 1) ? (len - 1 - t) : t;
            ci = indice[orig * KK + tt];
        }
        childs[tid] = ci;
    }
    __syncthreads();

    const __half* Hin = &g_Hf16[t & 1][gd][0];
    const size_t bblk = (size_t)(gd * 4 + ntile) * 8;

    float acc[2][8][4];                      // warp tile 32x64: [mt2][nf8][quad]
#pragma unroll
    for (int mt = 0; mt < 2; mt++)
#pragma unroll
        for (int nf = 0; nf < 8; nf++)
#pragma unroll
            for (int u = 0; u < 4; u++) acc[mt][nf][u] = 0.f;

    const int mw = wid & 3, nw = wid >> 2;   // 4 x 4 warp grid
    const int m0w = mw * 32, n0w = nw * 64;
    const int am = lane >> 3, ar = lane & 7;

    auto stage = [&](int c) {
        uint32_t base = sb + (c % 3) * BUF_B;
        uint32_t aS = base;
        uint32_t bS = base + SPA;
#pragma unroll
        for (int i = 0; i < 2; i++) {       // A: 1024 segs of 16B
            int g = tid + i * NT;
            int row = g >> 3, seg = g & 7;
            const __half* src;
            if (c < 4) src = g_hf16 + (size_t)childs[row] * 256 + c * 64 + seg * 8;
            else       src = Hin + (size_t)(m0 + row) * 256 + (c - 4) * 64 + seg * 8;
            CP_ASYNC16(aS + row * 144 + seg * 16, src);
        }
        const __half* bw = g_Bpf + (bblk + c) * 16384u;
#pragma unroll
        for (int i = 0; i < 4; i++) {       // B: 2048 segs of 16B
            int g = tid + i * NT;
            int row = g >> 3, seg = g & 7;
            CP_ASYNC16(bS + row * 144 + seg * 16, bw + row * 64 + seg * 8);
        }
        CP_COMMIT();
    };

    auto compute = [&](int c) {
        uint32_t base = sb + (c % 3) * BUF_B;
        uint32_t aS = base;
        uint32_t bS = base + SPA;
#pragma unroll
        for (int ks = 0; ks < 4; ks++) {
            int k0 = ks * 16;
            uint32_t af[2][4];
            int arow_off = ((am & 1) ? 8 : 0) + ar;
            int akk = (k0 + ((am >= 2) ? 8 : 0)) * 2;
#pragma unroll
            for (int mt = 0; mt < 2; mt++) {
                uint32_t off = (uint32_t)(m0w + mt * 16 + arow_off) * 144 + akk;
                ldsm4(af[mt], aS + off);
            }
            int brow_off = ((am >= 2) ? 8 : 0) + ar;
            int bkk = (k0 + ((am & 1) ? 8 : 0)) * 2;
#pragma unroll
            for (int np = 0; np < 4; np++) {
                uint32_t off = (uint32_t)(n0w + np * 16 + brow_off) * 144 + bkk;
                uint32_t rb[4];
                ldsm4(rb, bS + off);
                uint32_t b0[2] = {rb[0], rb[1]}, b1[2] = {rb[2], rb[3]};
#pragma unroll
                for (int mt = 0; mt < 2; mt++) {
                    mma_f16(acc[mt][np * 2], af[mt], b0);
                    mma_f16(acc[mt][np * 2 + 1], af[mt], b1);
                }
            }
        }
    };

    stage(0);
    stage(1);
#pragma unroll
    for (int c = 0; c < 8; c++) {
        if (c == 7) { CP_WAIT(0); } else { CP_WAIT(1); }
        __syncthreads();
        if (c + 2 < 8) stage(c + 2);
        compute(c);
    }
    __syncthreads();

    // epilogue: accums -> smem (stride 264), then pointwise LSTM
    float* zs = (float*)smem;    // [128][264]
#pragma unroll
    for (int mt = 0; mt < 2; mt++)
#pragma unroll
        for (int nf = 0; nf < 8; nf++) {
            int row = m0w + mt * 16 + (lane >> 2);
            int col = n0w + nf * 8 + (lane & 3) * 2;
            zs[row * 264 + col]           = acc[mt][nf][0];
            zs[row * 264 + col + 1]       = acc[mt][nf][1];
            zs[(row + 8) * 264 + col]     = acc[mt][nf][2];
            zs[(row + 8) * 264 + col + 1] = acc[mt][nf][3];
        }
    __syncthreads();

    const int dsel = gd & 1;
    const bool isG0 = gd < 2;
    const int par = (t + 1) & 1;
    const int cntNext = (t < 15) ? g_cnt[t + 1] : 0;   // rows with len == t+1: s >= cntNext
#pragma unroll
    for (int i = 0; i < 16; i++) {
        int e = tid + i * NT;               // 128 rows x 64 dims
        int row = e >> 6, d = e & 63;
        int s = m0 + row;
        if (s < Mact) {
            int jb = ntile * 64 + d;
            float zi = zs[row * 264 + 4 * d + 0] + lb[gd * 1024 + jb];
            float zf = zs[row * 264 + 4 * d + 1] + lb[gd * 1024 + 256 + jb];
            float zu = zs[row * 264 + 4 * d + 2] + lb[gd * 1024 + 512 + jb];
            float zo = zs[row * 264 + 4 * d + 3] + lb[gd * 1024 + 768 + jb];
            size_t off = (size_t)s * DIMM + jb;
            float cnew = sigm(zf) * g_C[gd][off] + sigm(zi) * tanhf(zu);
            float hnew = sigm(zo) * tanhf(cnew);
            g_C[gd][off] = cnew;
            __half hh = __float2half(hnew);
            g_Hf16[par][gd][off] = hh;
            if (isG0) g_Yf16[dsel][((size_t)s * KK + t) * DIMM + jb] = hh;
            if (s >= cntNext) g_Hfin[gd][off] = hh;    // t == len-1: final h
        }
    }
}

// ---- generic HMMA fc GEMM: C[M,256] = [A0|A1][M,512] @ Bp^T, same tile scheme ----
// mode 0: f_seq (M=NN*KK);  mode g in 1..3: y_last gate g (M=NN)
__global__ __launch_bounds__(NT, 1) void gemm_fc_kernel(int mode) {
    extern __shared__ __align__(1024) char smem[];
    const int m0 = blockIdx.x * 128;
    const int tid = threadIdx.x;
    const int wid = tid >> 5, lane = tid & 31;
    const uint32_t sb = smem_u32(smem);

    const __half *A0, *A1, *Bp;
    float* Cout;
    if (mode == 0) {
        A0 = g_Yf16[0]; A1 = g_Yf16[1];
        Bp = g_fcp; Cout = g_fseq;
    } else {
        A0 = g_Hfin[2 * mode]; A1 = g_Hfin[2 * mode + 1];
        Bp = g_fcp + (size_t)mode * 131072u;
        Cout = g_ydot + (size_t)(mode - 1) * NN * DIMM;
    }

    float acc[2][8][4];
#pragma unroll
    for (int mt = 0; mt < 2; mt++)
#pragma unroll
        for (int nf = 0; nf < 8; nf++)
#pragma unroll
            for (int u = 0; u < 4; u++) acc[mt][nf][u] = 0.f;

    const int mw = wid & 3, nw = wid >> 2;
    const int m0w = mw * 32, n0w = nw * 64;
    const int am = lane >> 3, ar = lane & 7;

    auto stage = [&](int c) {
        uint32_t base = sb + (c % 3) * BUF_B;
        uint32_t aS = base;
        uint32_t bS = base + SPA;
#pragma unroll
        for (int i = 0; i < 2; i++) {
            int g = tid + i * NT;
            int row = g >> 3, seg = g & 7;
            const __half* src = (c < 4)
                ? A0 + (size_t)(m0 + row) * 256 + c * 64 + seg * 8
                : A1 + (size_t)(m0 + row) * 256 + (c - 4) * 64 + seg * 8;
            CP_ASYNC16(aS + row * 144 + seg * 16, src);
        }
#pragma unroll
        for (int i = 0; i < 4; i++) {
            int g = tid + i * NT;
            int row = g >> 3, seg = g & 7;   // row = n index, Bp stride 512
            CP_ASYNC16(bS + row * 144 + seg * 16, Bp + (size_t)row * 512 + c * 64 + seg * 8);
        }
        CP_COMMIT();
    };

    auto compute = [&](int c) {
        uint32_t base = sb + (c % 3) * BUF_B;
        uint32_t aS = base;
        uint32_t bS = base + SPA;
#pragma unroll
        for (int ks = 0; ks < 4; ks++) {
            int k0 = ks * 16;
            uint32_t af[2][4];
            int arow_off = ((am & 1) ? 8 : 0) + ar;
            int akk = (k0 + ((am >= 2) ? 8 : 0)) * 2;
#pragma unroll
            for (int mt = 0; mt < 2; mt++) {
                uint32_t off = (uint32_t)(m0w + mt * 16 + arow_off) * 144 + akk;
                ldsm4(af[mt], aS + off);
            }
            int brow_off = ((am >= 2) ? 8 : 0) + ar;
            int bkk = (k0 + ((am & 1) ? 8 : 0)) * 2;
#pragma unroll
            for (int np = 0; np < 4; np++) {
                uint32_t off = (uint32_t)(n0w + np * 16 + brow_off) * 144 + bkk;
                uint32_t rb[4];
                ldsm4(rb, bS + off);
                uint32_t b0[2] = {rb[0], rb[1]}, b1[2] = {rb[2], rb[3]};
#pragma unroll
                for (int mt = 0; mt < 2; mt++) {
                    mma_f16(acc[mt][np * 2], af[mt], b0);
                    mma_f16(acc[mt][np * 2 + 1], af[mt], b1);
                }
            }
        }
    };

    stage(0);
    stage(1);
#pragma unroll
    for (int c = 0; c < 8; c++) {
        if (c == 7) { CP_WAIT(0); } else { CP_WAIT(1); }
        __syncthreads();
        if (c + 2 < 8) stage(c + 2);
        compute(c);
    }
    __syncthreads();

    float* zs = (float*)smem;    // [128][264]
#pragma unroll
    for (int mt = 0; mt < 2; mt++)
#pragma unroll
        for (int nf = 0; nf < 8; nf++) {
            int row = m0w + mt * 16 + (lane >> 2);
            int col = n0w + nf * 8 + (lane & 3) * 2;
            zs[row * 264 + col]           = acc[mt][nf][0];
            zs[row * 264 + col + 1]       = acc[mt][nf][1];
            zs[(row + 8) * 264 + col]     = acc[mt][nf][2];
            zs[(row + 8) * 264 + col + 1] = acc[mt][nf][3];
        }
    __syncthreads();

#pragma unroll
    for (int i = 0; i < 16; i++) {          // 128 rows x 64 float4s
        int e = tid + i * NT;
        int row = e >> 6, q = e & 63;
        float4 v = make_float4(zs[row * 264 + q * 4], zs[row * 264 + q * 4 + 1],
                               zs[row * 264 + q * 4 + 2], zs[row * 264 + q * 4 + 3]);
        *(float4*)&Cout[(size_t)(m0 + row) * 256 + q * 4] = v;
    }
}

// ---------------- final combine (light) ----------------
__global__ __launch_bounds__(256) void combine_kernel(
    const float* __restrict__ c_tensor, const int* __restrict__ indice,
    float* __restrict__ out) {
    int s = blockIdx.x;
    int j = threadIdx.x;
    int orig = g_sorted_orig[s];
    int len  = g_sorted_len[s];

    __shared__ int ciS[KK];
    if (j < KK) ciS[j] = (j < len) ? indice[orig * KK + j] : 0;
    __syncthreads();

    float Wf = g_Wx[orig * 1024 + j];
    float bf = 0.f;
    for (int t = 0; t < len; t++) {
        float fs = g_fseq[((size_t)s * KK + t) * DIMM + j];
        bf += sigm(Wf + fs) * c_tensor[(size_t)ciS[t] * DIMM + j];
    }

    float d0 = g_ydot[(size_t)0 * NN * DIMM + (size_t)s * DIMM + j];
    float d1 = g_ydot[(size_t)1 * NN * DIMM + (size_t)s * DIMM + j];
    float d2 = g_ydot[(size_t)2 * NN * DIMM + (size_t)s * DIMM + j];

    float Wi = g_Wx[orig * 1024 + 256 + j];
    float Wu = g_Wx[orig * 1024 + 512 + j];
    float Wo = g_Wx[orig * 1024 + 768 + j];
    float bi = sigm(d0 + Wi);
    float bu = tanhf(d1 + Wu);
    float bo = sigm(d2 + Wo);
    float nc = bi * bu + bf;
    float nh = bo * tanhf(nc);
    out[(size_t)orig * DIMM + j] = nh;
    out[(size_t)NN * DIMM + (size_t)orig * DIMM + j] = nc;
}

// ---------------- launch ----------------
extern "C" void kernel_launch(void* const* d_in, const int* in_sizes, int n_in,
                              void* d_out, int out_size) {
    const float* x        = (const float*)d_in[0];
    const float* h_tensor = (const float*)d_in[1];
    const float* c_tensor = (const float*)d_in[2];
    const int*   indice   = (const int*)d_in[3];
    const float* W_w      = (const float*)d_in[4];
    const float* W_b      = (const float*)d_in[5];
    const float* lk       = (const float*)d_in[6];
    const float* lr       = (const float*)d_in[7];
    const float* lb       = (const float*)d_in[8];
    const float* ih       = (const float*)d_in[9];
    const float* ic       = (const float*)d_in[10];
    const float* fc       = (const float*)d_in[11];
    float* out = (float*)d_out;

    cudaFuncSetAttribute(step_mma_kernel, cudaFuncAttributeMaxDynamicSharedMemorySize,
                         SMEM_STEP);
    cudaFuncSetAttribute(gemm_fc_kernel, cudaFuncAttributeMaxDynamicSharedMemorySize,
                         SMEM_STEP);

    zero_hist_kernel<<<1, 32>>>();
    len_hist_kernel<<<NN / 256, 256>>>(indice);
    prefix_kernel<<<1, 1>>>();
    scatter_kernel<<<NN / 256, 256>>>(indice);
    prep_kernel<<<(GD * NN * DIMM) / 256, 256>>>(ih, ic, lk, lr, h_tensor, fc);
    for (int t = 0; t < 16; t++)
        step_mma_kernel<<<dim3(32, 4, 8), NT, SMEM_STEP>>>(t, indice, lb);
    gemm_fc_kernel<<<NN * KK / 128, NT, SMEM_STEP>>>(0);          // f_seq
    for (int g = 1; g <= 3; g++)
        gemm_fc_kernel<<<NN / 128, NT, SMEM_STEP>>>(g);           // y_last gates
    wx_gemm_kernel<<<dim3(64, 16), 256>>>(x, W_w, W_b);
    combine_kernel<<<NN, 256>>>(c_tensor, indice, out);
}